// round 14
// baseline (speedup 1.0000x reference)
#include <cuda_runtime.h>
#include <cuda_bf16.h>
#include <cstdint>

#define NMAX 50000
#define NPAD 50048          // 391 tiles * 128 rows
#define EMAX 600000
#define DIM 128
#define BN_EPS 1e-5f

// ---------------- device scratch (no allocations allowed) ----------------
__device__ int   g_cnt[NMAX];
__device__ int   g_start[NMAX + 1];
__device__ int   g_cursor[NMAX];
__device__ int   g_src[EMAX];        // CSR: source node id per slot (layers 1/2)
__device__ int   g_src2[EMAX];       // CSR: x_idx[source] per slot (layer 0, emb row)
__device__ int   g_bsum[64];
__device__ float g_deg_inv[NMAX];
__device__ float g_dis[NMAX];
__device__ __align__(16) float g_h[NMAX * DIM];      // GEMM output (fp32)
__device__ __align__(16) float g_z[NMAX * DIM];      // dis * relu(bn(h)) for next gather
__device__ __align__(16) float g_stats[2][256];      // per-BN-layer col sum / sumsq

// bf16 split images, row-major. A: [NPAD][256 bf16] (=128 u32). Layers 1/2 use cols 0..127.
__device__ __align__(16) uint32_t g_ahi[(size_t)NPAD * 128];
__device__ __align__(16) uint32_t g_alo[(size_t)NPAD * 128];
// B: [sel][128 n][128 k] bf16 = 8192 u32. sel: 0=W_out 1=W_root 2=W_sg1 3=W_sg2
__device__ __align__(16) uint32_t g_bhi[4][8192];
__device__ __align__(16) uint32_t g_blo[4][8192];

// ---------------- helpers ----------------
__device__ __forceinline__ uint32_t smem_u32(const void* p) {
    uint32_t a;
    asm("{ .reg .u64 t; cvta.to.shared.u64 t, %1; cvt.u32.u64 %0, t; }" : "=r"(a) : "l"(p));
    return a;
}
// pack two floats to bf16x2 (low half = first arg)
__device__ __forceinline__ uint32_t bf16pair(float lo, float hi) {
    uint32_t r;
    asm("cvt.rn.bf16x2.f32 %0, %1, %2;" : "=r"(r) : "f"(hi), "f"(lo));
    return r;
}
__device__ __forceinline__ float lo_f(uint32_t p) { return __uint_as_float(p << 16); }
__device__ __forceinline__ float hi_f(uint32_t p) { return __uint_as_float(p & 0xFFFF0000u); }

__device__ __forceinline__ void ldmx4(uint32_t* r, uint32_t addr) {
    asm volatile("ldmatrix.sync.aligned.m8n8.x4.shared.b16 {%0,%1,%2,%3}, [%4];"
                 : "=r"(r[0]), "=r"(r[1]), "=r"(r[2]), "=r"(r[3]) : "r"(addr));
}
__device__ __forceinline__ void ldmx2(uint32_t* r, uint32_t addr) {
    asm volatile("ldmatrix.sync.aligned.m8n8.x2.shared.b16 {%0,%1}, [%2];"
                 : "=r"(r[0]), "=r"(r[1]) : "r"(addr));
}
__device__ __forceinline__ void mma16816(float* d, const uint32_t* a, const uint32_t* b) {
    asm volatile("mma.sync.aligned.m16n8k16.row.col.f32.bf16.bf16.f32 "
                 "{%0,%1,%2,%3}, {%4,%5,%6,%7}, {%8,%9}, {%0,%1,%2,%3};"
                 : "+f"(d[0]), "+f"(d[1]), "+f"(d[2]), "+f"(d[3])
                 : "r"(a[0]), "r"(a[1]), "r"(a[2]), "r"(a[3]), "r"(b[0]), "r"(b[1]));
}

// ---------------- init ----------------
__global__ void init_zero_kernel(int n) {
    int i = blockIdx.x * blockDim.x + threadIdx.x;
    if (i < n) g_cnt[i] = 0;
    if (i < 512) ((float*)g_stats)[i] = 0.f;
}

// ---------------- degree histogram + weight-image prep (merged launch) ----------------
// blocks [0, nbEdge): degree histogram; blocks [nbEdge, nbEdge+128): bprep
__global__ void deg_bprep_kernel(const int* __restrict__ col, int E, int nbEdge,
                                 const float* __restrict__ W_out, const float* __restrict__ W_root,
                                 const float* __restrict__ W_sg1, const float* __restrict__ W_sg2) {
    if (blockIdx.x < (unsigned)nbEdge) {
        int e = blockIdx.x * blockDim.x + threadIdx.x;
        if (e < E) atomicAdd(&g_cnt[col[e]], 1);
    } else {
        int t = (blockIdx.x - nbEdge) * blockDim.x + threadIdx.x;  // 0 .. 32767
        if (t >= 4 * 8192) return;
        int sel = t >> 13;
        int rem = t & 8191;
        int n = rem >> 6;
        int k = (rem & 63) << 1;
        const float* W = (sel == 0) ? W_out : (sel == 1) ? W_root : (sel == 2) ? W_sg1 : W_sg2;
        float x = __ldg(W + n * 128 + k);
        float y = __ldg(W + n * 128 + k + 1);
        uint32_t p = bf16pair(x, y);
        uint32_t q = bf16pair(x - lo_f(p), y - hi_f(p));
        g_bhi[sel][rem] = p;
        g_blo[sel][rem] = q;
    }
}

// ---------------- prefix scan (2 kernels, shuffle-based) ----------------
__global__ void scan1_kernel(int N) {
    __shared__ int wsum[8];
    int b = blockIdx.x, t = threadIdx.x;
    int lane = t & 31, wid = t >> 5;
    int base = b * 1024 + t * 4;
    int s = 0;
#pragma unroll
    for (int q = 0; q < 4; q++) { int idx = base + q; if (idx < N) s += g_cnt[idx]; }
    int v = s;
#pragma unroll
    for (int d = 16; d > 0; d >>= 1) v += __shfl_down_sync(0xFFFFFFFFu, v, d);
    if (lane == 0) wsum[wid] = v;
    __syncthreads();
    if (t == 0) {
        int tot = 0;
#pragma unroll
        for (int w = 0; w < 8; w++) tot += wsum[w];
        g_bsum[b] = tot;
    }
}
// scan3: shuffle-scan; computes its own block offset from g_bsum (<=64 blocks), writes
// offsets, cursors, and node norms (deg_inv / dis). All accesses coalesced. 2 barriers.
__global__ void scan3_kernel(int N, int E) {
    __shared__ int wtot[8];
    __shared__ int woff[8];
    __shared__ int sboff;
    int b = blockIdx.x, t = threadIdx.x;
    int lane = t & 31, wid = t >> 5;

    if (wid == 1) {
        int v0 = (lane < b) ? g_bsum[lane] : 0;
        int v1 = (lane + 32 < b) ? g_bsum[lane + 32] : 0;
        int v = v0 + v1;
#pragma unroll
        for (int d = 16; d > 0; d >>= 1) v += __shfl_down_sync(0xFFFFFFFFu, v, d);
        if (lane == 0) sboff = v;
    }

    int base = b * 1024 + t * 4;
    int v[4]; int s = 0;
#pragma unroll
    for (int q = 0; q < 4; q++) { int idx = base + q; v[q] = (idx < N) ? g_cnt[idx] : 0; s += v[q]; }

    int inc = s;
#pragma unroll
    for (int d = 1; d < 32; d <<= 1) {
        int y = __shfl_up_sync(0xFFFFFFFFu, inc, d);
        if (lane >= d) inc += y;
    }
    if (lane == 31) wtot[wid] = inc;
    __syncthreads();

    if (wid == 0 && lane < 8) {
        int w = wtot[lane];
#pragma unroll
        for (int d = 1; d < 8; d <<= 1) {
            int y = __shfl_up_sync(0xFFu, w, d);
            if (lane >= d) w += y;
        }
        woff[lane] = w - wtot[lane];
    }
    __syncthreads();

    int run = (inc - s) + woff[wid] + sboff;
#pragma unroll
    for (int q = 0; q < 4; q++) {
        int idx = base + q;
        if (idx < N) {
            g_start[idx] = run;
            g_cursor[idx] = run;
            run += v[q];
            float d = (float)v[q];
            g_deg_inv[idx] = 1.0f / fmaxf(d, 1.0f);
            g_dis[idx] = rsqrtf(d + 1.0f);
        }
    }
    if (b == 0 && t == 0) g_start[N] = E;
}
// fill: also stores the emb-row index (x_idx[r]) so gather0 avoids a dependent load
__global__ void fill_kernel(const int* __restrict__ edge, const int* __restrict__ x_idx, int E) {
    int e = blockIdx.x * blockDim.x + threadIdx.x;
    if (e < E) {
        int r = __ldg(edge + e);
        int c = __ldg(edge + E + e);
        int pos = atomicAdd(&g_cursor[c], 1);
        g_src[pos] = r;
        g_src2[pos] = __ldg(x_idx + r);
    }
}

__device__ __forceinline__ void write_split4(uint32_t* hi, uint32_t* lo, int idx2, float4 v) {
    uint32_t p0 = bf16pair(v.x, v.y);
    uint32_t p1 = bf16pair(v.z, v.w);
    uint32_t q0 = bf16pair(v.x - lo_f(p0), v.y - hi_f(p0));
    uint32_t q1 = bf16pair(v.z - lo_f(p1), v.w - hi_f(p1));
    reinterpret_cast<uint2*>(hi)[idx2] = make_uint2(p0, p1);
    reinterpret_cast<uint2*>(lo)[idx2] = make_uint2(q0, q1);
}

// ---------------- gather: one warp per node; writes bf16 split A rows ----------------
// SRC=0 (layer 0): rows via g_src2 (pre-resolved emb rows) -> 2-deep load chain
// SRC=1 (SGConv):  rows via g_src into g_z
template <int SRC>
__global__ void gather_kernel(const float* __restrict__ emb,
                              const int* __restrict__ x_idx, int N) {
    int t = blockIdx.x * blockDim.x + threadIdx.x;
    int n = t >> 5;
    if (n >= N) return;
    int lane = t & 31;
    int s = __ldg(&g_start[n]);
    int e = __ldg(&g_start[n + 1]);
    float4 a0 = make_float4(0.f, 0.f, 0.f, 0.f);
    float4 a1 = make_float4(0.f, 0.f, 0.f, 0.f);
    const int* srcIdx = (SRC == 0) ? g_src2 : g_src;
    const float* base = (SRC == 0) ? emb : g_z;
    int i = s;
    for (; i + 2 <= e; i += 2) {
        int r0 = __ldg(&srcIdx[i]);
        int r1 = __ldg(&srcIdx[i + 1]);
        const float* p0 = base + (size_t)r0 * DIM;
        const float* p1 = base + (size_t)r1 * DIM;
        float4 v0 = __ldg(reinterpret_cast<const float4*>(p0) + lane);
        float4 v1 = __ldg(reinterpret_cast<const float4*>(p1) + lane);
        a0.x += v0.x; a0.y += v0.y; a0.z += v0.z; a0.w += v0.w;
        a1.x += v1.x; a1.y += v1.y; a1.z += v1.z; a1.w += v1.w;
    }
    if (i < e) {
        int r0 = __ldg(&srcIdx[i]);
        const float* p0 = base + (size_t)r0 * DIM;
        float4 v0 = __ldg(reinterpret_cast<const float4*>(p0) + lane);
        a0.x += v0.x; a0.y += v0.y; a0.z += v0.z; a0.w += v0.w;
    }
    a0.x += a1.x; a0.y += a1.y; a0.z += a1.z; a0.w += a1.w;

    uint32_t* Ah = g_ahi + (size_t)n * 128;
    uint32_t* Al = g_alo + (size_t)n * 128;

    if (SRC == 0) {
        float sc = g_deg_inv[n];
        write_split4(Ah, Al, lane,
                     make_float4(sc * a0.x, sc * a0.y, sc * a0.z, sc * a0.w));
        const float* pr = emb + (size_t)__ldg(x_idx + n) * DIM;
        float4 vr = __ldg(reinterpret_cast<const float4*>(pr) + lane);
        write_split4(Ah, Al, 32 + lane, vr);
    } else {
        float sc = g_dis[n];
        float4 z = __ldg(reinterpret_cast<const float4*>(g_z + (size_t)n * DIM) + lane);
        write_split4(Ah, Al, lane,
                     make_float4(sc * (a0.x + z.x), sc * (a0.y + z.y),
                                 sc * (a0.z + z.z), sc * (a0.w + z.w)));
    }
}

// ---------------- mma.sync GEMM: 128x128 tile per block, bf16 3-term split ----------------
// smem rows padded to 17 x 16B (272B) -> conflict-free ldmatrix
#define SROW 272
#define OFF_AHI 0
#define OFF_ALO 34816
#define OFF_BHI 69632
#define OFF_BLO 104448
#define SMEM_BYTES 139264

template <int KCHUNKS, bool STATS, bool BIAS>
__global__ __launch_bounds__(256, 1)
void mma_kernel(const float* __restrict__ bias, float* __restrict__ H,
                float* __restrict__ stats, int N, int bsel) {
    extern __shared__ __align__(16) char smem[];
    __shared__ float sstats[256];

    const int tid = threadIdx.x;
    const int wid = tid >> 5;
    const int lane = tid & 31;
    const int tile = blockIdx.x;
    const int warpRow = wid & 3;        // 4 row groups of 32
    const int warpCol = wid >> 2;       // 2 col groups of 64

    sstats[tid] = 0.f;

    const uint32_t smemu = smem_u32(smem);

    float acc[2][8][4];
#pragma unroll
    for (int mt = 0; mt < 2; mt++)
#pragma unroll
        for (int nt = 0; nt < 8; nt++)
#pragma unroll
            for (int q = 0; q < 4; q++) acc[mt][nt][q] = 0.f;

    uint32_t aAddr[2][2];   // [mt][hi/lo]
#pragma unroll
    for (int mt = 0; mt < 2; mt++) {
        uint32_t rb = (uint32_t)(warpRow * 32 + mt * 16 + (lane & 15)) * SROW + ((lane >> 4) << 4);
        aAddr[mt][0] = smemu + OFF_AHI + rb;
        aAddr[mt][1] = smemu + OFF_ALO + rb;
    }
    uint32_t bRow = (uint32_t)(warpCol * 64 + (lane & 7)) * SROW + (((lane >> 3) & 1) << 4);
    uint32_t bAddrHi = smemu + OFF_BHI + bRow;
    uint32_t bAddrLo = smemu + OFF_BLO + bRow;

#pragma unroll
    for (int c = 0; c < KCHUNKS; c++) {
        __syncthreads();
        {
            const int4* gAh = (const int4*)(g_ahi + ((size_t)tile * 128) * 128) + c * 16;
            const int4* gAl = (const int4*)(g_alo + ((size_t)tile * 128) * 128) + c * 16;
            const int4* gBh = (const int4*)(g_bhi[bsel + c]);
            const int4* gBl = (const int4*)(g_blo[bsel + c]);
            int4* sAh = (int4*)(smem + OFF_AHI);
            int4* sAl = (int4*)(smem + OFF_ALO);
            int4* sBh = (int4*)(smem + OFF_BHI);
            int4* sBl = (int4*)(smem + OFF_BLO);
#pragma unroll
            for (int it = 0; it < 8; it++) {
                int idx = tid + it * 256;           // 0..2047
                int r = idx >> 4;
                int ch = idx & 15;
                int sIdx = r * 17 + ch;
                sAh[sIdx] = __ldg(gAh + r * 32 + ch);   // A global row stride 512B = 32 int4
                sAl[sIdx] = __ldg(gAl + r * 32 + ch);
                sBh[sIdx] = __ldg(gBh + r * 16 + ch);   // B global row stride 256B = 16 int4
                sBl[sIdx] = __ldg(gBl + r * 16 + ch);
            }
        }
        __syncthreads();

#pragma unroll
        for (int ks = 0; ks < 8; ks++) {
            uint32_t ahi[2][4], alo[2][4];
#pragma unroll
            for (int mt = 0; mt < 2; mt++) {
                ldmx4(ahi[mt], aAddr[mt][0] + ks * 32);
                ldmx4(alo[mt], aAddr[mt][1] + ks * 32);
            }
#pragma unroll
            for (int nt = 0; nt < 8; nt++) {
                uint32_t bhi[2], blo[2];
                ldmx2(bhi, bAddrHi + nt * (8 * SROW) + ks * 32);
                ldmx2(blo, bAddrLo + nt * (8 * SROW) + ks * 32);
#pragma unroll
                for (int mt = 0; mt < 2; mt++) {
                    mma16816(acc[mt][nt], ahi[mt], bhi);
                    mma16816(acc[mt][nt], ahi[mt], blo);
                    mma16816(acc[mt][nt], alo[mt], bhi);
                }
            }
        }
    }

    // ---- epilogue: bias + store + BN stats ----
    const int rowbase = tile * 128 + warpRow * 32;
    const int colbase = warpCol * 64;

    float s[8][2], q[8][2];
#pragma unroll
    for (int nt = 0; nt < 8; nt++) { s[nt][0] = s[nt][1] = 0.f; q[nt][0] = q[nt][1] = 0.f; }

#pragma unroll
    for (int mt = 0; mt < 2; mt++) {
        int r0 = rowbase + mt * 16 + (lane >> 2);
        int r1 = r0 + 8;
#pragma unroll
        for (int nt = 0; nt < 8; nt++) {
            int col = colbase + nt * 8 + ((lane & 3) << 1);
            float b0 = BIAS ? __ldg(bias + col) : 0.f;
            float b1 = BIAS ? __ldg(bias + col + 1) : 0.f;
            float v0 = acc[mt][nt][0] + b0;
            float v1 = acc[mt][nt][1] + b1;
            float v2 = acc[mt][nt][2] + b0;
            float v3 = acc[mt][nt][3] + b1;
            if (r0 < N) {
                *(float2*)(H + (size_t)r0 * DIM + col) = make_float2(v0, v1);
                if (STATS) {
                    s[nt][0] += v0; s[nt][1] += v1;
                    q[nt][0] += v0 * v0; q[nt][1] += v1 * v1;
                }
            }
            if (r1 < N) {
                *(float2*)(H + (size_t)r1 * DIM + col) = make_float2(v2, v3);
                if (STATS) {
                    s[nt][0] += v2; s[nt][1] += v3;
                    q[nt][0] += v2 * v2; q[nt][1] += v3 * v3;
                }
            }
        }
    }

    if (STATS) {
#pragma unroll
        for (int nt = 0; nt < 8; nt++) {
#pragma unroll
            for (int p = 0; p < 2; p++) {
                float vs = s[nt][p], vq = q[nt][p];
#pragma unroll
                for (int sh = 4; sh < 32; sh <<= 1) {
                    vs += __shfl_xor_sync(0xFFFFFFFFu, vs, sh);
                    vq += __shfl_xor_sync(0xFFFFFFFFu, vq, sh);
                }
                if (lane < 4) {
                    int col = colbase + nt * 8 + (lane << 1) + p;
                    atomicAdd(&sstats[col], vs);
                    atomicAdd(&sstats[128 + col], vq);
                }
            }
        }
        __syncthreads();
        atomicAdd(&stats[tid], sstats[tid]);
    }
}

// ---------------- BN apply + ReLU + dis-prescale (z = dis * relu(bn(h))) ----------------
// inline BN finalize: first 32 threads compute the 128 scale/shift params into smem
__global__ void bn_apply_kernel(const float* __restrict__ gamma, const float* __restrict__ beta,
                                const float* __restrict__ stats, int N) {
    __shared__ float4 ssc[32], ssh[32];
    int tid = threadIdx.x;
    if (tid < 32) {
        float4 s = ((const float4*)stats)[tid];
        float4 sq = ((const float4*)stats)[32 + tid];
        float4 g = __ldg((const float4*)gamma + tid);
        float4 b = __ldg((const float4*)beta + tid);
        float invn = 1.0f / (float)N;
        float4 mu = make_float4(s.x * invn, s.y * invn, s.z * invn, s.w * invn);
        float4 sc, sh;
        sc.x = g.x * rsqrtf(fmaxf(sq.x * invn - mu.x * mu.x, 0.f) + BN_EPS);
        sc.y = g.y * rsqrtf(fmaxf(sq.y * invn - mu.y * mu.y, 0.f) + BN_EPS);
        sc.z = g.z * rsqrtf(fmaxf(sq.z * invn - mu.z * mu.z, 0.f) + BN_EPS);
        sc.w = g.w * rsqrtf(fmaxf(sq.w * invn - mu.w * mu.w, 0.f) + BN_EPS);
        sh.x = b.x - mu.x * sc.x;
        sh.y = b.y - mu.y * sc.y;
        sh.z = b.z - mu.z * sc.z;
        sh.w = b.w - mu.w * sc.w;
        ssc[tid] = sc; ssh[tid] = sh;
    }
    __syncthreads();
    int i = blockIdx.x * blockDim.x + tid;
    int tot = N * (DIM / 4);
    if (i >= tot) return;
    int n = i >> 5;
    int q = i & 31;
    float4 h = reinterpret_cast<const float4*>(g_h)[i];
    float4 sc = ssc[q];
    float4 sh = ssh[q];
    float d = g_dis[n];
    float4 z;
    z.x = d * fmaxf(fmaf(h.x, sc.x, sh.x), 0.f);
    z.y = d * fmaxf(fmaf(h.y, sc.y, sh.y), 0.f);
    z.z = d * fmaxf(fmaf(h.z, sc.z, sh.z), 0.f);
    z.w = d * fmaxf(fmaf(h.w, sc.w, sh.w), 0.f);
    reinterpret_cast<float4*>(g_z)[i] = z;
}

// ---------------- launch ----------------
extern "C" void kernel_launch(void* const* d_in, const int* in_sizes, int n_in,
                              void* d_out, int out_size) {
    const int*   x_idx  = (const int*)d_in[0];
    const int*   edge   = (const int*)d_in[1];
    const float* emb    = (const float*)d_in[2];
    const float* W_out  = (const float*)d_in[3];
    const float* W_root = (const float*)d_in[4];
    const float* bn0_g  = (const float*)d_in[5];
    const float* bn0_b  = (const float*)d_in[6];
    const float* W_sg1  = (const float*)d_in[7];
    const float* b_sg1  = (const float*)d_in[8];
    const float* bn1_g  = (const float*)d_in[9];
    const float* bn1_b  = (const float*)d_in[10];
    const float* W_sg2  = (const float*)d_in[11];
    const float* b_sg2  = (const float*)d_in[12];
    float* out = (float*)d_out;

    int N = in_sizes[0];
    int E = in_sizes[1] / 2;

    void* hp = nullptr;   cudaGetSymbolAddress(&hp, g_h);
    void* sp = nullptr;   cudaGetSymbolAddress(&sp, g_stats);
    float* Hbuf = (float*)hp;
    float* stats0 = (float*)sp;
    float* stats1 = stats0 + 256;

    cudaFuncSetAttribute(mma_kernel<2, true, false>, cudaFuncAttributeMaxDynamicSharedMemorySize, SMEM_BYTES);
    cudaFuncSetAttribute(mma_kernel<1, true, true>,  cudaFuncAttributeMaxDynamicSharedMemorySize, SMEM_BYTES);
    cudaFuncSetAttribute(mma_kernel<1, false, true>, cudaFuncAttributeMaxDynamicSharedMemorySize, SMEM_BYTES);

    const int nbElem = (N * (DIM / 4) + 255) / 256;
    const int nbNode = (N + 255) / 256;
    const int nbEdgeT = (E + 255) / 256;
    const int nbGath = (N * 32 + 255) / 256;
    const int nbScan = (N + 1023) / 1024;
    const int NT = (N + 127) / 128;

    // CSR build + norms + weight images
    init_zero_kernel<<<nbNode, 256>>>(N);
    deg_bprep_kernel<<<nbEdgeT + 128, 256>>>(edge + E, E, nbEdgeT, W_out, W_root, W_sg1, W_sg2);
    scan1_kernel<<<nbScan, 256>>>(N);
    scan3_kernel<<<nbScan, 256>>>(N, E);
    fill_kernel<<<nbEdgeT, 256>>>(edge, x_idx, E);

    // layer 0: ClusterGCN -> BN -> ReLU
    gather_kernel<0><<<nbGath, 256>>>(emb, x_idx, N);
    mma_kernel<2, true, false><<<NT, 256, SMEM_BYTES>>>(nullptr, Hbuf, stats0, N, 0);
    bn_apply_kernel<<<nbElem, 256>>>(bn0_g, bn0_b, stats0, N);

    // layer 1: SGConv -> BN -> ReLU
    gather_kernel<1><<<nbGath, 256>>>(emb, x_idx, N);
    mma_kernel<1, true, true><<<NT, 256, SMEM_BYTES>>>(b_sg1, Hbuf, stats1, N, 2);
    bn_apply_kernel<<<nbElem, 256>>>(bn1_g, bn1_b, stats1, N);

    // layer 2: final SGConv -> d_out
    gather_kernel<1><<<nbGath, 256>>>(emb, x_idx, N);
    mma_kernel<1, false, true><<<NT, 256, SMEM_BYTES>>>(b_sg2, out, nullptr, N, 3);
}

// round 15
// speedup vs baseline: 1.0464x; 1.0464x over previous
#include <cuda_runtime.h>
#include <cuda_bf16.h>
#include <cstdint>

#define NMAX 50000
#define NPAD 50048          // 391 tiles * 128 rows
#define EMAX 600000
#define DIM 128
#define BN_EPS 1e-5f

// PDL: wait for predecessor grid's memory flush / allow dependents to launch.
// No-ops when the kernel wasn't launched with programmatic stream serialization.
#define GDC_WAIT()    asm volatile("griddepcontrol.wait;" ::: "memory")
#define GDC_TRIGGER() asm volatile("griddepcontrol.launch_dependents;" ::: "memory")

// ---------------- device scratch (no allocations allowed) ----------------
__device__ int   g_cnt[NMAX];
__device__ int   g_start[NMAX + 1];
__device__ int   g_cursor[NMAX];
__device__ int   g_src[EMAX];
__device__ int   g_bsum[64];
__device__ float g_deg_inv[NMAX];
__device__ float g_dis[NMAX];
__device__ __align__(16) float g_h[NMAX * DIM];      // GEMM output (fp32)
__device__ __align__(16) float g_z[NMAX * DIM];      // dis * relu(bn(h)) for next gather
__device__ __align__(16) float g_stats[2][256];      // per-BN-layer col sum / sumsq

// bf16 split images, row-major. A: [NPAD][256 bf16] (=128 u32). Layers 1/2 use cols 0..127.
__device__ __align__(16) uint32_t g_ahi[(size_t)NPAD * 128];
__device__ __align__(16) uint32_t g_alo[(size_t)NPAD * 128];
// B: [sel][128 n][128 k] bf16 = 8192 u32. sel: 0=W_out 1=W_root 2=W_sg1 3=W_sg2
__device__ __align__(16) uint32_t g_bhi[4][8192];
__device__ __align__(16) uint32_t g_blo[4][8192];

// ---------------- helpers ----------------
__device__ __forceinline__ uint32_t smem_u32(const void* p) {
    uint32_t a;
    asm("{ .reg .u64 t; cvta.to.shared.u64 t, %1; cvt.u32.u64 %0, t; }" : "=r"(a) : "l"(p));
    return a;
}
// pack two floats to bf16x2 (low half = first arg)
__device__ __forceinline__ uint32_t bf16pair(float lo, float hi) {
    uint32_t r;
    asm("cvt.rn.bf16x2.f32 %0, %1, %2;" : "=r"(r) : "f"(hi), "f"(lo));
    return r;
}
__device__ __forceinline__ float lo_f(uint32_t p) { return __uint_as_float(p << 16); }
__device__ __forceinline__ float hi_f(uint32_t p) { return __uint_as_float(p & 0xFFFF0000u); }

__device__ __forceinline__ void ldmx4(uint32_t* r, uint32_t addr) {
    asm volatile("ldmatrix.sync.aligned.m8n8.x4.shared.b16 {%0,%1,%2,%3}, [%4];"
                 : "=r"(r[0]), "=r"(r[1]), "=r"(r[2]), "=r"(r[3]) : "r"(addr));
}
__device__ __forceinline__ void ldmx2(uint32_t* r, uint32_t addr) {
    asm volatile("ldmatrix.sync.aligned.m8n8.x2.shared.b16 {%0,%1}, [%2];"
                 : "=r"(r[0]), "=r"(r[1]) : "r"(addr));
}
__device__ __forceinline__ void mma16816(float* d, const uint32_t* a, const uint32_t* b) {
    asm volatile("mma.sync.aligned.m16n8k16.row.col.f32.bf16.bf16.f32 "
                 "{%0,%1,%2,%3}, {%4,%5,%6,%7}, {%8,%9}, {%0,%1,%2,%3};"
                 : "+f"(d[0]), "+f"(d[1]), "+f"(d[2]), "+f"(d[3])
                 : "r"(a[0]), "r"(a[1]), "r"(a[2]), "r"(a[3]), "r"(b[0]), "r"(b[1]));
}

// ---------------- init ----------------
__global__ void init_zero_kernel(int n) {
    int i = blockIdx.x * blockDim.x + threadIdx.x;
    GDC_TRIGGER();
    if (i < n) g_cnt[i] = 0;
    if (i < 512) ((float*)g_stats)[i] = 0.f;
}

// ---------------- degree histogram + weight-image prep (merged launch) ----------------
// blocks [0, nbEdge): degree histogram; blocks [nbEdge, nbEdge+128): bprep
__global__ void deg_bprep_kernel(const int* __restrict__ col, int E, int nbEdge,
                                 const float* __restrict__ W_out, const float* __restrict__ W_root,
                                 const float* __restrict__ W_sg1, const float* __restrict__ W_sg2) {
    GDC_WAIT();
    GDC_TRIGGER();
    if (blockIdx.x < (unsigned)nbEdge) {
        int e = blockIdx.x * blockDim.x + threadIdx.x;
        if (e < E) atomicAdd(&g_cnt[col[e]], 1);
    } else {
        int t = (blockIdx.x - nbEdge) * blockDim.x + threadIdx.x;  // 0 .. 32767
        if (t >= 4 * 8192) return;
        int sel = t >> 13;
        int rem = t & 8191;
        int n = rem >> 6;
        int k = (rem & 63) << 1;
        const float* W = (sel == 0) ? W_out : (sel == 1) ? W_root : (sel == 2) ? W_sg1 : W_sg2;
        float x = __ldg(W + n * 128 + k);
        float y = __ldg(W + n * 128 + k + 1);
        uint32_t p = bf16pair(x, y);
        uint32_t q = bf16pair(x - lo_f(p), y - hi_f(p));
        g_bhi[sel][rem] = p;
        g_blo[sel][rem] = q;
    }
}

// ---------------- prefix scan (2 kernels, shuffle-based) ----------------
__global__ void scan1_kernel(int N) {
    __shared__ int wsum[8];
    GDC_WAIT();
    GDC_TRIGGER();
    int b = blockIdx.x, t = threadIdx.x;
    int lane = t & 31, wid = t >> 5;
    int base = b * 1024 + t * 4;
    int s = 0;
#pragma unroll
    for (int q = 0; q < 4; q++) { int idx = base + q; if (idx < N) s += g_cnt[idx]; }
    int v = s;
#pragma unroll
    for (int d = 16; d > 0; d >>= 1) v += __shfl_down_sync(0xFFFFFFFFu, v, d);
    if (lane == 0) wsum[wid] = v;
    __syncthreads();
    if (t == 0) {
        int tot = 0;
#pragma unroll
        for (int w = 0; w < 8; w++) tot += wsum[w];
        g_bsum[b] = tot;
    }
}
// scan3: shuffle-scan; computes its own block offset from g_bsum (<=64 blocks), writes
// offsets, cursors, and node norms (deg_inv / dis). All accesses coalesced. 2 barriers.
__global__ void scan3_kernel(int N, int E) {
    __shared__ int wtot[8];
    __shared__ int woff[8];
    __shared__ int sboff;
    GDC_WAIT();
    GDC_TRIGGER();
    int b = blockIdx.x, t = threadIdx.x;
    int lane = t & 31, wid = t >> 5;

    if (wid == 1) {
        int v0 = (lane < b) ? g_bsum[lane] : 0;
        int v1 = (lane + 32 < b) ? g_bsum[lane + 32] : 0;
        int v = v0 + v1;
#pragma unroll
        for (int d = 16; d > 0; d >>= 1) v += __shfl_down_sync(0xFFFFFFFFu, v, d);
        if (lane == 0) sboff = v;
    }

    int base = b * 1024 + t * 4;
    int v[4]; int s = 0;
#pragma unroll
    for (int q = 0; q < 4; q++) { int idx = base + q; v[q] = (idx < N) ? g_cnt[idx] : 0; s += v[q]; }

    int inc = s;
#pragma unroll
    for (int d = 1; d < 32; d <<= 1) {
        int y = __shfl_up_sync(0xFFFFFFFFu, inc, d);
        if (lane >= d) inc += y;
    }
    if (lane == 31) wtot[wid] = inc;
    __syncthreads();

    if (wid == 0 && lane < 8) {
        int w = wtot[lane];
#pragma unroll
        for (int d = 1; d < 8; d <<= 1) {
            int y = __shfl_up_sync(0xFFu, w, d);
            if (lane >= d) w += y;
        }
        woff[lane] = w - wtot[lane];
    }
    __syncthreads();

    int run = (inc - s) + woff[wid] + sboff;
#pragma unroll
    for (int q = 0; q < 4; q++) {
        int idx = base + q;
        if (idx < N) {
            g_start[idx] = run;
            g_cursor[idx] = run;
            run += v[q];
            float d = (float)v[q];
            g_deg_inv[idx] = 1.0f / fmaxf(d, 1.0f);
            g_dis[idx] = rsqrtf(d + 1.0f);
        }
    }
    if (b == 0 && t == 0) g_start[N] = E;
}
__global__ void fill_kernel(const int* __restrict__ edge, int E) {
    GDC_WAIT();
    GDC_TRIGGER();
    int e = blockIdx.x * blockDim.x + threadIdx.x;
    if (e < E) {
        int r = __ldg(edge + e);
        int c = __ldg(edge + E + e);
        int pos = atomicAdd(&g_cursor[c], 1);
        g_src[pos] = r;
    }
}

__device__ __forceinline__ void write_split4(uint32_t* hi, uint32_t* lo, int idx2, float4 v) {
    uint32_t p0 = bf16pair(v.x, v.y);
    uint32_t p1 = bf16pair(v.z, v.w);
    uint32_t q0 = bf16pair(v.x - lo_f(p0), v.y - hi_f(p0));
    uint32_t q1 = bf16pair(v.z - lo_f(p1), v.w - hi_f(p1));
    reinterpret_cast<uint2*>(hi)[idx2] = make_uint2(p0, p1);
    reinterpret_cast<uint2*>(lo)[idx2] = make_uint2(q0, q1);
}

// ---------------- gather: one warp per node; writes bf16 split A rows ----------------
// SRC=0 (layer 0): cols 0..127 = deg_inv[n]*sum(emb[x_idx[r]]); cols 128..255 = emb[x_idx[n]]
// SRC=1 (SGConv):  cols 0..127 = dis[n]*(sum(g_z[r]) + g_z[n]),  z already dis-prescaled
template <int SRC>
__global__ void gather_kernel(const float* __restrict__ emb,
                              const int* __restrict__ x_idx, int N) {
    GDC_WAIT();
    GDC_TRIGGER();
    int t = blockIdx.x * blockDim.x + threadIdx.x;
    int n = t >> 5;
    if (n >= N) return;
    int lane = t & 31;
    int s = __ldg(&g_start[n]);
    int e = __ldg(&g_start[n + 1]);
    float4 a0 = make_float4(0.f, 0.f, 0.f, 0.f);
    float4 a1 = make_float4(0.f, 0.f, 0.f, 0.f);
    int i = s;
    for (; i + 2 <= e; i += 2) {
        int r0 = __ldg(&g_src[i]);
        int r1 = __ldg(&g_src[i + 1]);
        const float* p0;
        const float* p1;
        if (SRC == 0) {
            p0 = emb + (size_t)__ldg(x_idx + r0) * DIM;
            p1 = emb + (size_t)__ldg(x_idx + r1) * DIM;
        } else {
            p0 = g_z + (size_t)r0 * DIM;
            p1 = g_z + (size_t)r1 * DIM;
        }
        float4 v0 = __ldg(reinterpret_cast<const float4*>(p0) + lane);
        float4 v1 = __ldg(reinterpret_cast<const float4*>(p1) + lane);
        a0.x += v0.x; a0.y += v0.y; a0.z += v0.z; a0.w += v0.w;
        a1.x += v1.x; a1.y += v1.y; a1.z += v1.z; a1.w += v1.w;
    }
    if (i < e) {
        int r0 = __ldg(&g_src[i]);
        const float* p0 = (SRC == 0) ? emb + (size_t)__ldg(x_idx + r0) * DIM
                                     : g_z + (size_t)r0 * DIM;
        float4 v0 = __ldg(reinterpret_cast<const float4*>(p0) + lane);
        a0.x += v0.x; a0.y += v0.y; a0.z += v0.z; a0.w += v0.w;
    }
    a0.x += a1.x; a0.y += a1.y; a0.z += a1.z; a0.w += a1.w;

    uint32_t* Ah = g_ahi + (size_t)n * 128;
    uint32_t* Al = g_alo + (size_t)n * 128;

    if (SRC == 0) {
        float sc = g_deg_inv[n];
        write_split4(Ah, Al, lane,
                     make_float4(sc * a0.x, sc * a0.y, sc * a0.z, sc * a0.w));
        const float* pr = emb + (size_t)__ldg(x_idx + n) * DIM;
        float4 vr = __ldg(reinterpret_cast<const float4*>(pr) + lane);
        write_split4(Ah, Al, 32 + lane, vr);
    } else {
        float sc = g_dis[n];
        float4 z = __ldg(reinterpret_cast<const float4*>(g_z + (size_t)n * DIM) + lane);
        write_split4(Ah, Al, lane,
                     make_float4(sc * (a0.x + z.x), sc * (a0.y + z.y),
                                 sc * (a0.z + z.z), sc * (a0.w + z.w)));
    }
}

// ---------------- mma.sync GEMM: 128x128 tile per block, bf16 3-term split ----------------
// smem rows padded to 17 x 16B (272B) -> conflict-free ldmatrix
#define SROW 272
#define OFF_AHI 0
#define OFF_ALO 34816
#define OFF_BHI 69632
#define OFF_BLO 104448
#define SMEM_BYTES 139264

template <int KCHUNKS, bool STATS, bool BIAS>
__global__ __launch_bounds__(256, 1)
void mma_kernel(const float* __restrict__ bias, float* __restrict__ H,
                float* __restrict__ stats, int N, int bsel) {
    extern __shared__ __align__(16) char smem[];
    __shared__ float sstats[256];

    GDC_WAIT();
    GDC_TRIGGER();

    const int tid = threadIdx.x;
    const int wid = tid >> 5;
    const int lane = tid & 31;
    const int tile = blockIdx.x;
    const int warpRow = wid & 3;        // 4 row groups of 32
    const int warpCol = wid >> 2;       // 2 col groups of 64

    sstats[tid] = 0.f;

    const uint32_t smemu = smem_u32(smem);

    float acc[2][8][4];
#pragma unroll
    for (int mt = 0; mt < 2; mt++)
#pragma unroll
        for (int nt = 0; nt < 8; nt++)
#pragma unroll
            for (int q = 0; q < 4; q++) acc[mt][nt][q] = 0.f;

    uint32_t aAddr[2][2];   // [mt][hi/lo]
#pragma unroll
    for (int mt = 0; mt < 2; mt++) {
        uint32_t rb = (uint32_t)(warpRow * 32 + mt * 16 + (lane & 15)) * SROW + ((lane >> 4) << 4);
        aAddr[mt][0] = smemu + OFF_AHI + rb;
        aAddr[mt][1] = smemu + OFF_ALO + rb;
    }
    uint32_t bRow = (uint32_t)(warpCol * 64 + (lane & 7)) * SROW + (((lane >> 3) & 1) << 4);
    uint32_t bAddrHi = smemu + OFF_BHI + bRow;
    uint32_t bAddrLo = smemu + OFF_BLO + bRow;

#pragma unroll
    for (int c = 0; c < KCHUNKS; c++) {
        __syncthreads();
        {
            const int4* gAh = (const int4*)(g_ahi + ((size_t)tile * 128) * 128) + c * 16;
            const int4* gAl = (const int4*)(g_alo + ((size_t)tile * 128) * 128) + c * 16;
            const int4* gBh = (const int4*)(g_bhi[bsel + c]);
            const int4* gBl = (const int4*)(g_blo[bsel + c]);
            int4* sAh = (int4*)(smem + OFF_AHI);
            int4* sAl = (int4*)(smem + OFF_ALO);
            int4* sBh = (int4*)(smem + OFF_BHI);
            int4* sBl = (int4*)(smem + OFF_BLO);
#pragma unroll
            for (int it = 0; it < 8; it++) {
                int idx = tid + it * 256;           // 0..2047
                int r = idx >> 4;
                int ch = idx & 15;
                int sIdx = r * 17 + ch;
                sAh[sIdx] = __ldg(gAh + r * 32 + ch);   // A global row stride 512B = 32 int4
                sAl[sIdx] = __ldg(gAl + r * 32 + ch);
                sBh[sIdx] = __ldg(gBh + r * 16 + ch);   // B global row stride 256B = 16 int4
                sBl[sIdx] = __ldg(gBl + r * 16 + ch);
            }
        }
        __syncthreads();

#pragma unroll
        for (int ks = 0; ks < 8; ks++) {
            uint32_t ahi[2][4], alo[2][4];
#pragma unroll
            for (int mt = 0; mt < 2; mt++) {
                ldmx4(ahi[mt], aAddr[mt][0] + ks * 32);
                ldmx4(alo[mt], aAddr[mt][1] + ks * 32);
            }
#pragma unroll
            for (int nt = 0; nt < 8; nt++) {
                uint32_t bhi[2], blo[2];
                ldmx2(bhi, bAddrHi + nt * (8 * SROW) + ks * 32);
                ldmx2(blo, bAddrLo + nt * (8 * SROW) + ks * 32);
#pragma unroll
                for (int mt = 0; mt < 2; mt++) {
                    mma16816(acc[mt][nt], ahi[mt], bhi);
                    mma16816(acc[mt][nt], ahi[mt], blo);
                    mma16816(acc[mt][nt], alo[mt], bhi);
                }
            }
        }
    }

    // ---- epilogue: bias + store + BN stats ----
    const int rowbase = tile * 128 + warpRow * 32;
    const int colbase = warpCol * 64;

    float s[8][2], q[8][2];
#pragma unroll
    for (int nt = 0; nt < 8; nt++) { s[nt][0] = s[nt][1] = 0.f; q[nt][0] = q[nt][1] = 0.f; }

#pragma unroll
    for (int mt = 0; mt < 2; mt++) {
        int r0 = rowbase + mt * 16 + (lane >> 2);
        int r1 = r0 + 8;
#pragma unroll
        for (int nt = 0; nt < 8; nt++) {
            int col = colbase + nt * 8 + ((lane & 3) << 1);
            float b0 = BIAS ? __ldg(bias + col) : 0.f;
            float b1 = BIAS ? __ldg(bias + col + 1) : 0.f;
            float v0 = acc[mt][nt][0] + b0;
            float v1 = acc[mt][nt][1] + b1;
            float v2 = acc[mt][nt][2] + b0;
            float v3 = acc[mt][nt][3] + b1;
            if (r0 < N) {
                *(float2*)(H + (size_t)r0 * DIM + col) = make_float2(v0, v1);
                if (STATS) {
                    s[nt][0] += v0; s[nt][1] += v1;
                    q[nt][0] += v0 * v0; q[nt][1] += v1 * v1;
                }
            }
            if (r1 < N) {
                *(float2*)(H + (size_t)r1 * DIM + col) = make_float2(v2, v3);
                if (STATS) {
                    s[nt][0] += v2; s[nt][1] += v3;
                    q[nt][0] += v2 * v2; q[nt][1] += v3 * v3;
                }
            }
        }
    }

    if (STATS) {
#pragma unroll
        for (int nt = 0; nt < 8; nt++) {
#pragma unroll
            for (int p = 0; p < 2; p++) {
                float vs = s[nt][p], vq = q[nt][p];
#pragma unroll
                for (int sh = 4; sh < 32; sh <<= 1) {
                    vs += __shfl_xor_sync(0xFFFFFFFFu, vs, sh);
                    vq += __shfl_xor_sync(0xFFFFFFFFu, vq, sh);
                }
                if (lane < 4) {
                    int col = colbase + nt * 8 + (lane << 1) + p;
                    atomicAdd(&sstats[col], vs);
                    atomicAdd(&sstats[128 + col], vq);
                }
            }
        }
        __syncthreads();
        atomicAdd(&stats[tid], sstats[tid]);
    }
}

// ---------------- BN apply + ReLU + dis-prescale (z = dis * relu(bn(h))) ----------------
// inline BN finalize: first 32 threads compute the 128 scale/shift params into smem
__global__ void bn_apply_kernel(const float* __restrict__ gamma, const float* __restrict__ beta,
                                const float* __restrict__ stats, int N) {
    __shared__ float4 ssc[32], ssh[32];
    GDC_WAIT();
    GDC_TRIGGER();
    int tid = threadIdx.x;
    if (tid < 32) {
        float4 s = ((const float4*)stats)[tid];
        float4 sq = ((const float4*)stats)[32 + tid];
        float4 g = __ldg((const float4*)gamma + tid);
        float4 b = __ldg((const float4*)beta + tid);
        float invn = 1.0f / (float)N;
        float4 mu = make_float4(s.x * invn, s.y * invn, s.z * invn, s.w * invn);
        float4 sc, sh;
        sc.x = g.x * rsqrtf(fmaxf(sq.x * invn - mu.x * mu.x, 0.f) + BN_EPS);
        sc.y = g.y * rsqrtf(fmaxf(sq.y * invn - mu.y * mu.y, 0.f) + BN_EPS);
        sc.z = g.z * rsqrtf(fmaxf(sq.z * invn - mu.z * mu.z, 0.f) + BN_EPS);
        sc.w = g.w * rsqrtf(fmaxf(sq.w * invn - mu.w * mu.w, 0.f) + BN_EPS);
        sh.x = b.x - mu.x * sc.x;
        sh.y = b.y - mu.y * sc.y;
        sh.z = b.z - mu.z * sc.z;
        sh.w = b.w - mu.w * sc.w;
        ssc[tid] = sc; ssh[tid] = sh;
    }
    __syncthreads();
    int i = blockIdx.x * blockDim.x + tid;
    int tot = N * (DIM / 4);
    if (i >= tot) return;
    int n = i >> 5;
    int q = i & 31;
    float4 h = reinterpret_cast<const float4*>(g_h)[i];
    float4 sc = ssc[q];
    float4 sh = ssh[q];
    float d = g_dis[n];
    float4 z;
    z.x = d * fmaxf(fmaf(h.x, sc.x, sh.x), 0.f);
    z.y = d * fmaxf(fmaf(h.y, sc.y, sh.y), 0.f);
    z.z = d * fmaxf(fmaf(h.z, sc.z, sh.z), 0.f);
    z.w = d * fmaxf(fmaf(h.w, sc.w, sh.w), 0.f);
    reinterpret_cast<float4*>(g_z)[i] = z;
}

// ---------------- PDL launch helpers ----------------
static inline void launch_pdl(void* func, dim3 grid, dim3 block, size_t smem,
                              void** args) {
    cudaLaunchConfig_t cfg = {};
    cfg.gridDim = grid;
    cfg.blockDim = block;
    cfg.dynamicSmemBytes = smem;
    cudaLaunchAttribute attr[1];
    attr[0].id = cudaLaunchAttributeProgrammaticStreamSerialization;
    attr[0].val.programmaticStreamSerializationAllowed = 1;
    cfg.attrs = attr;
    cfg.numAttrs = 1;
    cudaLaunchKernelExC(&cfg, func, args);
}

// ---------------- launch ----------------
extern "C" void kernel_launch(void* const* d_in, const int* in_sizes, int n_in,
                              void* d_out, int out_size) {
    const int*   x_idx  = (const int*)d_in[0];
    const int*   edge   = (const int*)d_in[1];
    const float* emb    = (const float*)d_in[2];
    const float* W_out  = (const float*)d_in[3];
    const float* W_root = (const float*)d_in[4];
    const float* bn0_g  = (const float*)d_in[5];
    const float* bn0_b  = (const float*)d_in[6];
    const float* W_sg1  = (const float*)d_in[7];
    const float* b_sg1  = (const float*)d_in[8];
    const float* bn1_g  = (const float*)d_in[9];
    const float* bn1_b  = (const float*)d_in[10];
    const float* W_sg2  = (const float*)d_in[11];
    const float* b_sg2  = (const float*)d_in[12];
    float* out = (float*)d_out;

    int N = in_sizes[0];
    int E = in_sizes[1] / 2;

    void* hp = nullptr;   cudaGetSymbolAddress(&hp, g_h);
    void* sp = nullptr;   cudaGetSymbolAddress(&sp, g_stats);
    float* Hbuf = (float*)hp;
    float* stats0 = (float*)sp;
    float* stats1 = stats0 + 256;

    cudaFuncSetAttribute(mma_kernel<2, true, false>, cudaFuncAttributeMaxDynamicSharedMemorySize, SMEM_BYTES);
    cudaFuncSetAttribute(mma_kernel<1, true, true>,  cudaFuncAttributeMaxDynamicSharedMemorySize, SMEM_BYTES);
    cudaFuncSetAttribute(mma_kernel<1, false, true>, cudaFuncAttributeMaxDynamicSharedMemorySize, SMEM_BYTES);

    const int nbElem = (N * (DIM / 4) + 255) / 256;
    const int nbNode = (N + 255) / 256;
    const int nbEdgeT = (E + 255) / 256;
    const int nbGath = (N * 32 + 255) / 256;
    const int nbScan = (N + 1023) / 1024;
    const int NT = (N + 127) / 128;
    const dim3 blk(256);

    // CSR build + norms + weight images
    {
        void* a[] = { (void*)&N };
        launch_pdl((void*)init_zero_kernel, dim3(nbNode), blk, 0, a);
    }
    {
        const int* colp = edge + E;
        void* a[] = { (void*)&colp, (void*)&E, (void*)&nbEdgeT,
                      (void*)&W_out, (void*)&W_root, (void*)&W_sg1, (void*)&W_sg2 };
        launch_pdl((void*)deg_bprep_kernel, dim3(nbEdgeT + 128), blk, 0, a);
    }
    {
        void* a[] = { (void*)&N };
        launch_pdl((void*)scan1_kernel, dim3(nbScan), blk, 0, a);
    }
    {
        void* a[] = { (void*)&N, (void*)&E };
        launch_pdl((void*)scan3_kernel, dim3(nbScan), blk, 0, a);
    }
    {
        void* a[] = { (void*)&edge, (void*)&E };
        launch_pdl((void*)fill_kernel, dim3(nbEdgeT), blk, 0, a);
    }

    // layer 0: ClusterGCN -> BN -> ReLU
    {
        void* a[] = { (void*)&emb, (void*)&x_idx, (void*)&N };
        launch_pdl((void*)gather_kernel<0>, dim3(nbGath), blk, 0, a);
    }
    {
        const float* bias = nullptr; int bsel = 0;
        void* a[] = { (void*)&bias, (void*)&Hbuf, (void*)&stats0, (void*)&N, (void*)&bsel };
        launch_pdl((void*)mma_kernel<2, true, false>, dim3(NT), blk, SMEM_BYTES, a);
    }
    {
        void* a[] = { (void*)&bn0_g, (void*)&bn0_b, (void*)&stats0, (void*)&N };
        launch_pdl((void*)bn_apply_kernel, dim3(nbElem), blk, 0, a);
    }

    // layer 1: SGConv -> BN -> ReLU
    {
        void* a[] = { (void*)&emb, (void*)&x_idx, (void*)&N };
        launch_pdl((void*)gather_kernel<1>, dim3(nbGath), blk, 0, a);
    }
    {
        int bsel = 2;
        void* a[] = { (void*)&b_sg1, (void*)&Hbuf, (void*)&stats1, (void*)&N, (void*)&bsel };
        launch_pdl((void*)mma_kernel<1, true, true>, dim3(NT), blk, SMEM_BYTES, a);
    }
    {
        void* a[] = { (void*)&bn1_g, (void*)&bn1_b, (void*)&stats1, (void*)&N };
        launch_pdl((void*)bn_apply_kernel, dim3(nbElem), blk, 0, a);
    }

    // layer 2: final SGConv -> d_out
    {
        void* a[] = { (void*)&emb, (void*)&x_idx, (void*)&N };
        launch_pdl((void*)gather_kernel<1>, dim3(nbGath), blk, 0, a);
    }
    {
        float* snull = nullptr; int bsel = 3;
        void* a[] = { (void*)&b_sg2, (void*)&out, (void*)&snull, (void*)&N, (void*)&bsel };
        launch_pdl((void*)mma_kernel<1, false, true>, dim3(NT), blk, SMEM_BYTES, a);
    }
}

// round 16
// speedup vs baseline: 1.0867x; 1.0385x over previous
#include <cuda_runtime.h>
#include <cuda_bf16.h>
#include <cuda_fp16.h>
#include <cstdint>

#define NMAX 50000
#define NPAD 50048          // 391 tiles * 128 rows
#define EMAX 600000
#define DIM 128
#define BN_EPS 1e-5f

// PDL: trigger lets dependents launch early; wait blocks until the predecessor
// grid has fully completed + flushed. Pre-wait code must only touch kernel inputs.
#define GDC_WAIT()    asm volatile("griddepcontrol.wait;" ::: "memory")
#define GDC_TRIGGER() asm volatile("griddepcontrol.launch_dependents;" ::: "memory")

// ---------------- device scratch (no allocations allowed) ----------------
__device__ int   g_cnt[NMAX];
__device__ int   g_start[NMAX + 1];
__device__ int   g_cursor[NMAX];
__device__ int   g_src[EMAX];
__device__ int   g_bsum[64];
__device__ float g_deg_inv[NMAX];
__device__ float g_dis[NMAX];
__device__ __align__(16) float g_h[NMAX * DIM];        // GEMM output (fp32)
__device__ __align__(16) uint32_t g_zh[NMAX * 64];     // z = dis*relu(bn(h)) as half2 pairs
__device__ __align__(16) float g_stats[2][256];        // per-BN-layer col sum / sumsq

// bf16 split images, row-major. A: [NPAD][256 bf16] (=128 u32). Layers 1/2 use cols 0..127.
__device__ __align__(16) uint32_t g_ahi[(size_t)NPAD * 128];
__device__ __align__(16) uint32_t g_alo[(size_t)NPAD * 128];
// B: [sel][128 n][128 k] bf16 = 8192 u32. sel: 0=W_out 1=W_root 2=W_sg1 3=W_sg2
__device__ __align__(16) uint32_t g_bhi[4][8192];
__device__ __align__(16) uint32_t g_blo[4][8192];

// ---------------- helpers ----------------
__device__ __forceinline__ uint32_t smem_u32(const void* p) {
    uint32_t a;
    asm("{ .reg .u64 t; cvta.to.shared.u64 t, %1; cvt.u32.u64 %0, t; }" : "=r"(a) : "l"(p));
    return a;
}
// pack two floats to bf16x2 (low half = first arg)
__device__ __forceinline__ uint32_t bf16pair(float lo, float hi) {
    uint32_t r;
    asm("cvt.rn.bf16x2.f32 %0, %1, %2;" : "=r"(r) : "f"(hi), "f"(lo));
    return r;
}
__device__ __forceinline__ float lo_f(uint32_t p) { return __uint_as_float(p << 16); }
__device__ __forceinline__ float hi_f(uint32_t p) { return __uint_as_float(p & 0xFFFF0000u); }

// half2-pair (uint2) -> float4
__device__ __forceinline__ float4 h2f4(uint2 u) {
    __half2 a = *reinterpret_cast<__half2*>(&u.x);
    __half2 b = *reinterpret_cast<__half2*>(&u.y);
    float2 fa = __half22float2(a);
    float2 fb = __half22float2(b);
    return make_float4(fa.x, fa.y, fb.x, fb.y);
}
// float4 -> half2-pair (uint2)
__device__ __forceinline__ uint2 f4h2(float4 v) {
    __half2 a = __floats2half2_rn(v.x, v.y);
    __half2 b = __floats2half2_rn(v.z, v.w);
    uint2 u;
    u.x = *reinterpret_cast<uint32_t*>(&a);
    u.y = *reinterpret_cast<uint32_t*>(&b);
    return u;
}

__device__ __forceinline__ void ldmx4(uint32_t* r, uint32_t addr) {
    asm volatile("ldmatrix.sync.aligned.m8n8.x4.shared.b16 {%0,%1,%2,%3}, [%4];"
                 : "=r"(r[0]), "=r"(r[1]), "=r"(r[2]), "=r"(r[3]) : "r"(addr));
}
__device__ __forceinline__ void ldmx2(uint32_t* r, uint32_t addr) {
    asm volatile("ldmatrix.sync.aligned.m8n8.x2.shared.b16 {%0,%1}, [%2];"
                 : "=r"(r[0]), "=r"(r[1]) : "r"(addr));
}
__device__ __forceinline__ void mma16816(float* d, const uint32_t* a, const uint32_t* b) {
    asm volatile("mma.sync.aligned.m16n8k16.row.col.f32.bf16.bf16.f32 "
                 "{%0,%1,%2,%3}, {%4,%5,%6,%7}, {%8,%9}, {%0,%1,%2,%3};"
                 : "+f"(d[0]), "+f"(d[1]), "+f"(d[2]), "+f"(d[3])
                 : "r"(a[0]), "r"(a[1]), "r"(a[2]), "r"(a[3]), "r"(b[0]), "r"(b[1]));
}

// ---------------- init ----------------
__global__ void init_zero_kernel(int n) {
    int i = blockIdx.x * blockDim.x + threadIdx.x;
    GDC_TRIGGER();
    if (i < n) g_cnt[i] = 0;
    if (i < 512) ((float*)g_stats)[i] = 0.f;
}

// ---------------- degree histogram + weight-image prep (merged launch) ----------------
__global__ void deg_bprep_kernel(const int* __restrict__ col, int E, int nbEdge,
                                 const float* __restrict__ W_out, const float* __restrict__ W_root,
                                 const float* __restrict__ W_sg1, const float* __restrict__ W_sg2) {
    GDC_WAIT();
    GDC_TRIGGER();
    if (blockIdx.x < (unsigned)nbEdge) {
        int e = blockIdx.x * blockDim.x + threadIdx.x;
        if (e < E) atomicAdd(&g_cnt[col[e]], 1);
    } else {
        int t = (blockIdx.x - nbEdge) * blockDim.x + threadIdx.x;  // 0 .. 32767
        if (t >= 4 * 8192) return;
        int sel = t >> 13;
        int rem = t & 8191;
        int n = rem >> 6;
        int k = (rem & 63) << 1;
        const float* W = (sel == 0) ? W_out : (sel == 1) ? W_root : (sel == 2) ? W_sg1 : W_sg2;
        float x = __ldg(W + n * 128 + k);
        float y = __ldg(W + n * 128 + k + 1);
        uint32_t p = bf16pair(x, y);
        uint32_t q = bf16pair(x - lo_f(p), y - hi_f(p));
        g_bhi[sel][rem] = p;
        g_blo[sel][rem] = q;
    }
}

// ---------------- prefix scan (2 kernels, shuffle-based) ----------------
__global__ void scan1_kernel(int N) {
    __shared__ int wsum[8];
    GDC_WAIT();
    GDC_TRIGGER();
    int b = blockIdx.x, t = threadIdx.x;
    int lane = t & 31, wid = t >> 5;
    int base = b * 1024 + t * 4;
    int s = 0;
#pragma unroll
    for (int q = 0; q < 4; q++) { int idx = base + q; if (idx < N) s += g_cnt[idx]; }
    int v = s;
#pragma unroll
    for (int d = 16; d > 0; d >>= 1) v += __shfl_down_sync(0xFFFFFFFFu, v, d);
    if (lane == 0) wsum[wid] = v;
    __syncthreads();
    if (t == 0) {
        int tot = 0;
#pragma unroll
        for (int w = 0; w < 8; w++) tot += wsum[w];
        g_bsum[b] = tot;
    }
}
__global__ void scan3_kernel(int N, int E) {
    __shared__ int wtot[8];
    __shared__ int woff[8];
    __shared__ int sboff;
    GDC_WAIT();
    GDC_TRIGGER();
    int b = blockIdx.x, t = threadIdx.x;
    int lane = t & 31, wid = t >> 5;

    if (wid == 1) {
        int v0 = (lane < b) ? g_bsum[lane] : 0;
        int v1 = (lane + 32 < b) ? g_bsum[lane + 32] : 0;
        int v = v0 + v1;
#pragma unroll
        for (int d = 16; d > 0; d >>= 1) v += __shfl_down_sync(0xFFFFFFFFu, v, d);
        if (lane == 0) sboff = v;
    }

    int base = b * 1024 + t * 4;
    int v[4]; int s = 0;
#pragma unroll
    for (int q = 0; q < 4; q++) { int idx = base + q; v[q] = (idx < N) ? g_cnt[idx] : 0; s += v[q]; }

    int inc = s;
#pragma unroll
    for (int d = 1; d < 32; d <<= 1) {
        int y = __shfl_up_sync(0xFFFFFFFFu, inc, d);
        if (lane >= d) inc += y;
    }
    if (lane == 31) wtot[wid] = inc;
    __syncthreads();

    if (wid == 0 && lane < 8) {
        int w = wtot[lane];
#pragma unroll
        for (int d = 1; d < 8; d <<= 1) {
            int y = __shfl_up_sync(0xFFu, w, d);
            if (lane >= d) w += y;
        }
        woff[lane] = w - wtot[lane];
    }
    __syncthreads();

    int run = (inc - s) + woff[wid] + sboff;
#pragma unroll
    for (int q = 0; q < 4; q++) {
        int idx = base + q;
        if (idx < N) {
            g_start[idx] = run;
            g_cursor[idx] = run;
            run += v[q];
            float d = (float)v[q];
            g_deg_inv[idx] = 1.0f / fmaxf(d, 1.0f);
            g_dis[idx] = rsqrtf(d + 1.0f);
        }
    }
    if (b == 0 && t == 0) g_start[N] = E;
}
__global__ void fill_kernel(const int* __restrict__ edge, int E) {
    GDC_WAIT();
    GDC_TRIGGER();
    int e = blockIdx.x * blockDim.x + threadIdx.x;
    if (e < E) {
        int r = __ldg(edge + e);
        int c = __ldg(edge + E + e);
        int pos = atomicAdd(&g_cursor[c], 1);
        g_src[pos] = r;
    }
}

__device__ __forceinline__ void write_split4(uint32_t* hi, uint32_t* lo, int idx2, float4 v) {
    uint32_t p0 = bf16pair(v.x, v.y);
    uint32_t p1 = bf16pair(v.z, v.w);
    uint32_t q0 = bf16pair(v.x - lo_f(p0), v.y - hi_f(p0));
    uint32_t q1 = bf16pair(v.z - lo_f(p1), v.w - hi_f(p1));
    reinterpret_cast<uint2*>(hi)[idx2] = make_uint2(p0, p1);
    reinterpret_cast<uint2*>(lo)[idx2] = make_uint2(q0, q1);
}

// ---------------- gather: one warp per node; writes bf16 split A rows ----------------
// SRC=0 (layer 0): cols 0..127 = deg_inv[n]*sum(emb[x_idx[r]]); cols 128..255 = emb[x_idx[n]]
// SRC=1 (SGConv):  cols 0..127 = dis[n]*(sum(zh[r]) + zh[n]),  z stored half2, dis-prescaled
template <int SRC>
__global__ void gather_kernel(const float* __restrict__ emb,
                              const int* __restrict__ x_idx, int N) {
    GDC_WAIT();
    GDC_TRIGGER();
    int t = blockIdx.x * blockDim.x + threadIdx.x;
    int n = t >> 5;
    if (n >= N) return;
    int lane = t & 31;
    int s = __ldg(&g_start[n]);
    int e = __ldg(&g_start[n + 1]);
    float4 a0 = make_float4(0.f, 0.f, 0.f, 0.f);
    float4 a1 = make_float4(0.f, 0.f, 0.f, 0.f);
    int i = s;
    for (; i + 2 <= e; i += 2) {
        int r0 = __ldg(&g_src[i]);
        int r1 = __ldg(&g_src[i + 1]);
        float4 v0, v1;
        if (SRC == 0) {
            const float* p0 = emb + (size_t)__ldg(x_idx + r0) * DIM;
            const float* p1 = emb + (size_t)__ldg(x_idx + r1) * DIM;
            v0 = __ldg(reinterpret_cast<const float4*>(p0) + lane);
            v1 = __ldg(reinterpret_cast<const float4*>(p1) + lane);
        } else {
            uint2 u0 = __ldg(reinterpret_cast<const uint2*>(g_zh) + (size_t)r0 * 32 + lane);
            uint2 u1 = __ldg(reinterpret_cast<const uint2*>(g_zh) + (size_t)r1 * 32 + lane);
            v0 = h2f4(u0);
            v1 = h2f4(u1);
        }
        a0.x += v0.x; a0.y += v0.y; a0.z += v0.z; a0.w += v0.w;
        a1.x += v1.x; a1.y += v1.y; a1.z += v1.z; a1.w += v1.w;
    }
    if (i < e) {
        int r0 = __ldg(&g_src[i]);
        float4 v0;
        if (SRC == 0) {
            const float* p0 = emb + (size_t)__ldg(x_idx + r0) * DIM;
            v0 = __ldg(reinterpret_cast<const float4*>(p0) + lane);
        } else {
            uint2 u0 = __ldg(reinterpret_cast<const uint2*>(g_zh) + (size_t)r0 * 32 + lane);
            v0 = h2f4(u0);
        }
        a0.x += v0.x; a0.y += v0.y; a0.z += v0.z; a0.w += v0.w;
    }
    a0.x += a1.x; a0.y += a1.y; a0.z += a1.z; a0.w += a1.w;

    uint32_t* Ah = g_ahi + (size_t)n * 128;
    uint32_t* Al = g_alo + (size_t)n * 128;

    if (SRC == 0) {
        float sc = g_deg_inv[n];
        write_split4(Ah, Al, lane,
                     make_float4(sc * a0.x, sc * a0.y, sc * a0.z, sc * a0.w));
        const float* pr = emb + (size_t)__ldg(x_idx + n) * DIM;
        float4 vr = __ldg(reinterpret_cast<const float4*>(pr) + lane);
        write_split4(Ah, Al, 32 + lane, vr);
    } else {
        float sc = g_dis[n];
        uint2 uz = __ldg(reinterpret_cast<const uint2*>(g_zh) + (size_t)n * 32 + lane);
        float4 z = h2f4(uz);
        write_split4(Ah, Al, lane,
                     make_float4(sc * (a0.x + z.x), sc * (a0.y + z.y),
                                 sc * (a0.z + z.z), sc * (a0.w + z.w)));
    }
}

// ---------------- mma.sync GEMM: 128x128 tile per block, bf16 3-term split ----------------
// smem rows padded to 17 x 16B (272B) -> conflict-free ldmatrix
#define SROW 272
#define OFF_AHI 0
#define OFF_ALO 34816
#define OFF_BHI 69632
#define OFF_BLO 104448
#define SMEM_BYTES 139264

template <int KCHUNKS, bool STATS, bool BIAS>
__global__ __launch_bounds__(256, 1)
void mma_kernel(const float* __restrict__ bias, float* __restrict__ H,
                float* __restrict__ stats, int N, int bsel) {
    extern __shared__ __align__(16) char smem[];
    __shared__ float sstats[256];

    GDC_WAIT();
    GDC_TRIGGER();

    const int tid = threadIdx.x;
    const int wid = tid >> 5;
    const int lane = tid & 31;
    const int tile = blockIdx.x;
    const int warpRow = wid & 3;        // 4 row groups of 32
    const int warpCol = wid >> 2;       // 2 col groups of 64

    sstats[tid] = 0.f;

    const uint32_t smemu = smem_u32(smem);

    float acc[2][8][4];
#pragma unroll
    for (int mt = 0; mt < 2; mt++)
#pragma unroll
        for (int nt = 0; nt < 8; nt++)
#pragma unroll
            for (int q = 0; q < 4; q++) acc[mt][nt][q] = 0.f;

    uint32_t aAddr[2][2];   // [mt][hi/lo]
#pragma unroll
    for (int mt = 0; mt < 2; mt++) {
        uint32_t rb = (uint32_t)(warpRow * 32 + mt * 16 + (lane & 15)) * SROW + ((lane >> 4) << 4);
        aAddr[mt][0] = smemu + OFF_AHI + rb;
        aAddr[mt][1] = smemu + OFF_ALO + rb;
    }
    uint32_t bRow = (uint32_t)(warpCol * 64 + (lane & 7)) * SROW + (((lane >> 3) & 1) << 4);
    uint32_t bAddrHi = smemu + OFF_BHI + bRow;
    uint32_t bAddrLo = smemu + OFF_BLO + bRow;

#pragma unroll
    for (int c = 0; c < KCHUNKS; c++) {
        __syncthreads();
        {
            const int4* gAh = (const int4*)(g_ahi + ((size_t)tile * 128) * 128) + c * 16;
            const int4* gAl = (const int4*)(g_alo + ((size_t)tile * 128) * 128) + c * 16;
            const int4* gBh = (const int4*)(g_bhi[bsel + c]);
            const int4* gBl = (const int4*)(g_blo[bsel + c]);
            int4* sAh = (int4*)(smem + OFF_AHI);
            int4* sAl = (int4*)(smem + OFF_ALO);
            int4* sBh = (int4*)(smem + OFF_BHI);
            int4* sBl = (int4*)(smem + OFF_BLO);
#pragma unroll
            for (int it = 0; it < 8; it++) {
                int idx = tid + it * 256;           // 0..2047
                int r = idx >> 4;
                int ch = idx & 15;
                int sIdx = r * 17 + ch;
                sAh[sIdx] = __ldg(gAh + r * 32 + ch);   // A global row stride 512B = 32 int4
                sAl[sIdx] = __ldg(gAl + r * 32 + ch);
                sBh[sIdx] = __ldg(gBh + r * 16 + ch);   // B global row stride 256B = 16 int4
                sBl[sIdx] = __ldg(gBl + r * 16 + ch);
            }
        }
        __syncthreads();

#pragma unroll
        for (int ks = 0; ks < 8; ks++) {
            uint32_t ahi[2][4], alo[2][4];
#pragma unroll
            for (int mt = 0; mt < 2; mt++) {
                ldmx4(ahi[mt], aAddr[mt][0] + ks * 32);
                ldmx4(alo[mt], aAddr[mt][1] + ks * 32);
            }
#pragma unroll
            for (int nt = 0; nt < 8; nt++) {
                uint32_t bhi[2], blo[2];
                ldmx2(bhi, bAddrHi + nt * (8 * SROW) + ks * 32);
                ldmx2(blo, bAddrLo + nt * (8 * SROW) + ks * 32);
#pragma unroll
                for (int mt = 0; mt < 2; mt++) {
                    mma16816(acc[mt][nt], ahi[mt], bhi);
                    mma16816(acc[mt][nt], ahi[mt], blo);
                    mma16816(acc[mt][nt], alo[mt], bhi);
                }
            }
        }
    }

    // ---- epilogue: bias + store + BN stats ----
    const int rowbase = tile * 128 + warpRow * 32;
    const int colbase = warpCol * 64;

    float s[8][2], q[8][2];
#pragma unroll
    for (int nt = 0; nt < 8; nt++) { s[nt][0] = s[nt][1] = 0.f; q[nt][0] = q[nt][1] = 0.f; }

#pragma unroll
    for (int mt = 0; mt < 2; mt++) {
        int r0 = rowbase + mt * 16 + (lane >> 2);
        int r1 = r0 + 8;
#pragma unroll
        for (int nt = 0; nt < 8; nt++) {
            int col = colbase + nt * 8 + ((lane & 3) << 1);
            float b0 = BIAS ? __ldg(bias + col) : 0.f;
            float b1 = BIAS ? __ldg(bias + col + 1) : 0.f;
            float v0 = acc[mt][nt][0] + b0;
            float v1 = acc[mt][nt][1] + b1;
            float v2 = acc[mt][nt][2] + b0;
            float v3 = acc[mt][nt][3] + b1;
            if (r0 < N) {
                *(float2*)(H + (size_t)r0 * DIM + col) = make_float2(v0, v1);
                if (STATS) {
                    s[nt][0] += v0; s[nt][1] += v1;
                    q[nt][0] += v0 * v0; q[nt][1] += v1 * v1;
                }
            }
            if (r1 < N) {
                *(float2*)(H + (size_t)r1 * DIM + col) = make_float2(v2, v3);
                if (STATS) {
                    s[nt][0] += v2; s[nt][1] += v3;
                    q[nt][0] += v2 * v2; q[nt][1] += v3 * v3;
                }
            }
        }
    }

    if (STATS) {
#pragma unroll
        for (int nt = 0; nt < 8; nt++) {
#pragma unroll
            for (int p = 0; p < 2; p++) {
                float vs = s[nt][p], vq = q[nt][p];
#pragma unroll
                for (int sh = 4; sh < 32; sh <<= 1) {
                    vs += __shfl_xor_sync(0xFFFFFFFFu, vs, sh);
                    vq += __shfl_xor_sync(0xFFFFFFFFu, vq, sh);
                }
                if (lane < 4) {
                    int col = colbase + nt * 8 + (lane << 1) + p;
                    atomicAdd(&sstats[col], vs);
                    atomicAdd(&sstats[128 + col], vq);
                }
            }
        }
        __syncthreads();
        atomicAdd(&stats[tid], sstats[tid]);
    }
}

// ---------------- BN apply + ReLU + dis-prescale; z stored as half2 ----------------
__global__ void bn_apply_kernel(const float* __restrict__ gamma, const float* __restrict__ beta,
                                const float* __restrict__ stats, int N) {
    __shared__ float4 ssc[32], ssh[32];
    GDC_WAIT();
    GDC_TRIGGER();
    int tid = threadIdx.x;
    if (tid < 32) {
        float4 s = ((const float4*)stats)[tid];
        float4 sq = ((const float4*)stats)[32 + tid];
        float4 g = __ldg((const float4*)gamma + tid);
        float4 b = __ldg((const float4*)beta + tid);
        float invn = 1.0f / (float)N;
        float4 mu = make_float4(s.x * invn, s.y * invn, s.z * invn, s.w * invn);
        float4 sc, sh;
        sc.x = g.x * rsqrtf(fmaxf(sq.x * invn - mu.x * mu.x, 0.f) + BN_EPS);
        sc.y = g.y * rsqrtf(fmaxf(sq.y * invn - mu.y * mu.y, 0.f) + BN_EPS);
        sc.z = g.z * rsqrtf(fmaxf(sq.z * invn - mu.z * mu.z, 0.f) + BN_EPS);
        sc.w = g.w * rsqrtf(fmaxf(sq.w * invn - mu.w * mu.w, 0.f) + BN_EPS);
        sh.x = b.x - mu.x * sc.x;
        sh.y = b.y - mu.y * sc.y;
        sh.z = b.z - mu.z * sc.z;
        sh.w = b.w - mu.w * sc.w;
        ssc[tid] = sc; ssh[tid] = sh;
    }
    __syncthreads();
    int i = blockIdx.x * blockDim.x + tid;
    int tot = N * (DIM / 4);
    if (i >= tot) return;
    int n = i >> 5;
    int q = i & 31;
    float4 h = reinterpret_cast<const float4*>(g_h)[i];
    float4 sc = ssc[q];
    float4 sh = ssh[q];
    float d = g_dis[n];
    float4 z;
    z.x = d * fmaxf(fmaf(h.x, sc.x, sh.x), 0.f);
    z.y = d * fmaxf(fmaf(h.y, sc.y, sh.y), 0.f);
    z.z = d * fmaxf(fmaf(h.z, sc.z, sh.z), 0.f);
    z.w = d * fmaxf(fmaf(h.w, sc.w, sh.w), 0.f);
    reinterpret_cast<uint2*>(g_zh)[i] = f4h2(z);
}

// ---------------- PDL launch helpers ----------------
static inline void launch_pdl(void* func, dim3 grid, dim3 block, size_t smem,
                              void** args) {
    cudaLaunchConfig_t cfg = {};
    cfg.gridDim = grid;
    cfg.blockDim = block;
    cfg.dynamicSmemBytes = smem;
    cudaLaunchAttribute attr[1];
    attr[0].id = cudaLaunchAttributeProgrammaticStreamSerialization;
    attr[0].val.programmaticStreamSerializationAllowed = 1;
    cfg.attrs = attr;
    cfg.numAttrs = 1;
    cudaLaunchKernelExC(&cfg, func, args);
}

// ---------------- launch ----------------
extern "C" void kernel_launch(void* const* d_in, const int* in_sizes, int n_in,
                              void* d_out, int out_size) {
    const int*   x_idx  = (const int*)d_in[0];
    const int*   edge   = (const int*)d_in[1];
    const float* emb    = (const float*)d_in[2];
    const float* W_out  = (const float*)d_in[3];
    const float* W_root = (const float*)d_in[4];
    const float* bn0_g  = (const float*)d_in[5];
    const float* bn0_b  = (const float*)d_in[6];
    const float* W_sg1  = (const float*)d_in[7];
    const float* b_sg1  = (const float*)d_in[8];
    const float* bn1_g  = (const float*)d_in[9];
    const float* bn1_b  = (const float*)d_in[10];
    const float* W_sg2  = (const float*)d_in[11];
    const float* b_sg2  = (const float*)d_in[12];
    float* out = (float*)d_out;

    int N = in_sizes[0];
    int E = in_sizes[1] / 2;

    void* hp = nullptr;   cudaGetSymbolAddress(&hp, g_h);
    void* sp = nullptr;   cudaGetSymbolAddress(&sp, g_stats);
    float* Hbuf = (float*)hp;
    float* stats0 = (float*)sp;
    float* stats1 = stats0 + 256;

    cudaFuncSetAttribute(mma_kernel<2, true, false>, cudaFuncAttributeMaxDynamicSharedMemorySize, SMEM_BYTES);
    cudaFuncSetAttribute(mma_kernel<1, true, true>,  cudaFuncAttributeMaxDynamicSharedMemorySize, SMEM_BYTES);
    cudaFuncSetAttribute(mma_kernel<1, false, true>, cudaFuncAttributeMaxDynamicSharedMemorySize, SMEM_BYTES);

    const int nbElem = (N * (DIM / 4) + 255) / 256;
    const int nbNode = (N + 255) / 256;
    const int nbEdgeT = (E + 255) / 256;
    const int nbGath = (N * 32 + 255) / 256;
    const int nbScan = (N + 1023) / 1024;
    const int NT = (N + 127) / 128;
    const dim3 blk(256);

    // CSR build + norms + weight images
    {
        void* a[] = { (void*)&N };
        launch_pdl((void*)init_zero_kernel, dim3(nbNode), blk, 0, a);
    }
    {
        const int* colp = edge + E;
        void* a[] = { (void*)&colp, (void*)&E, (void*)&nbEdgeT,
                      (void*)&W_out, (void*)&W_root, (void*)&W_sg1, (void*)&W_sg2 };
        launch_pdl((void*)deg_bprep_kernel, dim3(nbEdgeT + 128), blk, 0, a);
    }
    {
        void* a[] = { (void*)&N };
        launch_pdl((void*)scan1_kernel, dim3(nbScan), blk, 0, a);
    }
    {
        void* a[] = { (void*)&N, (void*)&E };
        launch_pdl((void*)scan3_kernel, dim3(nbScan), blk, 0, a);
    }
    {
        void* a[] = { (void*)&edge, (void*)&E };
        launch_pdl((void*)fill_kernel, dim3(nbEdgeT), blk, 0, a);
    }

    // layer 0: ClusterGCN -> BN -> ReLU
    {
        void* a[] = { (void*)&emb, (void*)&x_idx, (void*)&N };
        launch_pdl((void*)gather_kernel<0>, dim3(nbGath), blk, 0, a);
    }
    {
        const float* bias = nullptr; int bsel = 0;
        void* a[] = { (void*)&bias, (void*)&Hbuf, (void*)&stats0, (void*)&N, (void*)&bsel };
        launch_pdl((void*)mma_kernel<2, true, false>, dim3(NT), blk, SMEM_BYTES, a);
    }
    {
        void* a[] = { (void*)&bn0_g, (void*)&bn0_b, (void*)&stats0, (void*)&N };
        launch_pdl((void*)bn_apply_kernel, dim3(nbElem), blk, 0, a);
    }

    // layer 1: SGConv -> BN -> ReLU
    {
        void* a[] = { (void*)&emb, (void*)&x_idx, (void*)&N };
        launch_pdl((void*)gather_kernel<1>, dim3(nbGath), blk, 0, a);
    }
    {
        int bsel = 2;
        void* a[] = { (void*)&b_sg1, (void*)&Hbuf, (void*)&stats1, (void*)&N, (void*)&bsel };
        launch_pdl((void*)mma_kernel<1, true, true>, dim3(NT), blk, SMEM_BYTES, a);
    }
    {
        void* a[] = { (void*)&bn1_g, (void*)&bn1_b, (void*)&stats1, (void*)&N };
        launch_pdl((void*)bn_apply_kernel, dim3(nbElem), blk, 0, a);
    }

    // layer 2: final SGConv -> d_out
    {
        void* a[] = { (void*)&emb, (void*)&x_idx, (void*)&N };
        launch_pdl((void*)gather_kernel<1>, dim3(nbGath), blk, 0, a);
    }
    {
        float* snull = nullptr; int bsel = 3;
        void* a[] = { (void*)&b_sg2, (void*)&out, (void*)&snull, (void*)&N, (void*)&bsel };
        launch_pdl((void*)mma_kernel<1, false, true>, dim3(NT), blk, SMEM_BYTES, a);
    }
}

// round 17
// speedup vs baseline: 1.0971x; 1.0096x over previous
#include <cuda_runtime.h>
#include <cuda_bf16.h>
#include <cuda_fp16.h>
#include <cstdint>

#define NMAX 50000
#define NPAD 50048          // 391 tiles * 128 rows
#define EMAX 600000
#define DIM 128
#define BN_EPS 1e-5f

// PDL: trigger lets dependents launch early; wait blocks until the predecessor
// grid has fully completed + flushed. Pre-wait code must only touch kernel inputs.
#define GDC_WAIT()    asm volatile("griddepcontrol.wait;" ::: "memory")
#define GDC_TRIGGER() asm volatile("griddepcontrol.launch_dependents;" ::: "memory")

// ---------------- device scratch (no allocations allowed) ----------------
__device__ int   g_cnt[NMAX];
__device__ int   g_start[NMAX + 1];
__device__ int   g_cursor[NMAX];
__device__ int   g_src[EMAX];
__device__ int   g_bsum[64];
__device__ float g_deg_inv[NMAX];
__device__ float g_dis[NMAX];
__device__ __align__(16) float g_h[NMAX * DIM];        // GEMM output (fp32)
__device__ __align__(16) uint32_t g_zh[NMAX * 64];     // z = dis*relu(bn(h)) as half2 pairs
__device__ __align__(16) uint32_t g_eh[NMAX * 64];     // emb table as half2 pairs
__device__ __align__(16) float g_stats[2][256];        // per-BN-layer col sum / sumsq

// bf16 split images, row-major. A: [NPAD][256 bf16] (=128 u32). Layers 1/2 use cols 0..127.
__device__ __align__(16) uint32_t g_ahi[(size_t)NPAD * 128];
__device__ __align__(16) uint32_t g_alo[(size_t)NPAD * 128];
// B: [sel][128 n][128 k] bf16 = 8192 u32. sel: 0=W_out 1=W_root 2=W_sg1 3=W_sg2
__device__ __align__(16) uint32_t g_bhi[4][8192];
__device__ __align__(16) uint32_t g_blo[4][8192];

// ---------------- helpers ----------------
__device__ __forceinline__ uint32_t smem_u32(const void* p) {
    uint32_t a;
    asm("{ .reg .u64 t; cvta.to.shared.u64 t, %1; cvt.u32.u64 %0, t; }" : "=r"(a) : "l"(p));
    return a;
}
// pack two floats to bf16x2 (low half = first arg)
__device__ __forceinline__ uint32_t bf16pair(float lo, float hi) {
    uint32_t r;
    asm("cvt.rn.bf16x2.f32 %0, %1, %2;" : "=r"(r) : "f"(hi), "f"(lo));
    return r;
}
__device__ __forceinline__ float lo_f(uint32_t p) { return __uint_as_float(p << 16); }
__device__ __forceinline__ float hi_f(uint32_t p) { return __uint_as_float(p & 0xFFFF0000u); }

// half2-pair (uint2) -> float4
__device__ __forceinline__ float4 h2f4(uint2 u) {
    __half2 a = *reinterpret_cast<__half2*>(&u.x);
    __half2 b = *reinterpret_cast<__half2*>(&u.y);
    float2 fa = __half22float2(a);
    float2 fb = __half22float2(b);
    return make_float4(fa.x, fa.y, fb.x, fb.y);
}
// float4 -> half2-pair (uint2)
__device__ __forceinline__ uint2 f4h2(float4 v) {
    __half2 a = __floats2half2_rn(v.x, v.y);
    __half2 b = __floats2half2_rn(v.z, v.w);
    uint2 u;
    u.x = *reinterpret_cast<uint32_t*>(&a);
    u.y = *reinterpret_cast<uint32_t*>(&b);
    return u;
}

__device__ __forceinline__ void ldmx4(uint32_t* r, uint32_t addr) {
    asm volatile("ldmatrix.sync.aligned.m8n8.x4.shared.b16 {%0,%1,%2,%3}, [%4];"
                 : "=r"(r[0]), "=r"(r[1]), "=r"(r[2]), "=r"(r[3]) : "r"(addr));
}
__device__ __forceinline__ void ldmx2(uint32_t* r, uint32_t addr) {
    asm volatile("ldmatrix.sync.aligned.m8n8.x2.shared.b16 {%0,%1}, [%2];"
                 : "=r"(r[0]), "=r"(r[1]) : "r"(addr));
}
__device__ __forceinline__ void mma16816(float* d, const uint32_t* a, const uint32_t* b) {
    asm volatile("mma.sync.aligned.m16n8k16.row.col.f32.bf16.bf16.f32 "
                 "{%0,%1,%2,%3}, {%4,%5,%6,%7}, {%8,%9}, {%0,%1,%2,%3};"
                 : "+f"(d[0]), "+f"(d[1]), "+f"(d[2]), "+f"(d[3])
                 : "r"(a[0]), "r"(a[1]), "r"(a[2]), "r"(a[3]), "r"(b[0]), "r"(b[1]));
}

// ---------------- init ----------------
__global__ void init_zero_kernel(int n) {
    int i = blockIdx.x * blockDim.x + threadIdx.x;
    GDC_TRIGGER();
    if (i < n) g_cnt[i] = 0;
    if (i < 512) ((float*)g_stats)[i] = 0.f;
}

// ---------------- degree histogram + weight-image prep + emb->fp16 (merged) ----------------
// blocks [0, nbEdge): degree histogram
// blocks [nbEdge, nbEdge+128): bprep
// blocks [nbEdge+128, ...): emb fp32 -> half2 conversion
__global__ void deg_bprep_kernel(const int* __restrict__ col, int E, int nbEdge, int N,
                                 const float* __restrict__ emb,
                                 const float* __restrict__ W_out, const float* __restrict__ W_root,
                                 const float* __restrict__ W_sg1, const float* __restrict__ W_sg2) {
    GDC_WAIT();
    GDC_TRIGGER();
    if (blockIdx.x < (unsigned)nbEdge) {
        int e = blockIdx.x * blockDim.x + threadIdx.x;
        if (e < E) atomicAdd(&g_cnt[col[e]], 1);
    } else if (blockIdx.x < (unsigned)(nbEdge + 128)) {
        int t = (blockIdx.x - nbEdge) * blockDim.x + threadIdx.x;  // 0 .. 32767
        if (t >= 4 * 8192) return;
        int sel = t >> 13;
        int rem = t & 8191;
        int n = rem >> 6;
        int k = (rem & 63) << 1;
        const float* W = (sel == 0) ? W_out : (sel == 1) ? W_root : (sel == 2) ? W_sg1 : W_sg2;
        float x = __ldg(W + n * 128 + k);
        float y = __ldg(W + n * 128 + k + 1);
        uint32_t p = bf16pair(x, y);
        uint32_t q = bf16pair(x - lo_f(p), y - hi_f(p));
        g_bhi[sel][rem] = p;
        g_blo[sel][rem] = q;
    } else {
        int i = (blockIdx.x - nbEdge - 128) * blockDim.x + threadIdx.x;  // float4 index
        if (i >= N * 32) return;
        float4 v = __ldg(reinterpret_cast<const float4*>(emb) + i);
        reinterpret_cast<uint2*>(g_eh)[i] = f4h2(v);
    }
}

// ---------------- prefix scan (2 kernels, shuffle-based) ----------------
__global__ void scan1_kernel(int N) {
    __shared__ int wsum[8];
    GDC_WAIT();
    GDC_TRIGGER();
    int b = blockIdx.x, t = threadIdx.x;
    int lane = t & 31, wid = t >> 5;
    int base = b * 1024 + t * 4;
    int s = 0;
#pragma unroll
    for (int q = 0; q < 4; q++) { int idx = base + q; if (idx < N) s += g_cnt[idx]; }
    int v = s;
#pragma unroll
    for (int d = 16; d > 0; d >>= 1) v += __shfl_down_sync(0xFFFFFFFFu, v, d);
    if (lane == 0) wsum[wid] = v;
    __syncthreads();
    if (t == 0) {
        int tot = 0;
#pragma unroll
        for (int w = 0; w < 8; w++) tot += wsum[w];
        g_bsum[b] = tot;
    }
}
__global__ void scan3_kernel(int N, int E) {
    __shared__ int wtot[8];
    __shared__ int woff[8];
    __shared__ int sboff;
    GDC_WAIT();
    GDC_TRIGGER();
    int b = blockIdx.x, t = threadIdx.x;
    int lane = t & 31, wid = t >> 5;

    if (wid == 1) {
        int v0 = (lane < b) ? g_bsum[lane] : 0;
        int v1 = (lane + 32 < b) ? g_bsum[lane + 32] : 0;
        int v = v0 + v1;
#pragma unroll
        for (int d = 16; d > 0; d >>= 1) v += __shfl_down_sync(0xFFFFFFFFu, v, d);
        if (lane == 0) sboff = v;
    }

    int base = b * 1024 + t * 4;
    int v[4]; int s = 0;
#pragma unroll
    for (int q = 0; q < 4; q++) { int idx = base + q; v[q] = (idx < N) ? g_cnt[idx] : 0; s += v[q]; }

    int inc = s;
#pragma unroll
    for (int d = 1; d < 32; d <<= 1) {
        int y = __shfl_up_sync(0xFFFFFFFFu, inc, d);
        if (lane >= d) inc += y;
    }
    if (lane == 31) wtot[wid] = inc;
    __syncthreads();

    if (wid == 0 && lane < 8) {
        int w = wtot[lane];
#pragma unroll
        for (int d = 1; d < 8; d <<= 1) {
            int y = __shfl_up_sync(0xFFu, w, d);
            if (lane >= d) w += y;
        }
        woff[lane] = w - wtot[lane];
    }
    __syncthreads();

    int run = (inc - s) + woff[wid] + sboff;
#pragma unroll
    for (int q = 0; q < 4; q++) {
        int idx = base + q;
        if (idx < N) {
            g_start[idx] = run;
            g_cursor[idx] = run;
            run += v[q];
            float d = (float)v[q];
            g_deg_inv[idx] = 1.0f / fmaxf(d, 1.0f);
            g_dis[idx] = rsqrtf(d + 1.0f);
        }
    }
    if (b == 0 && t == 0) g_start[N] = E;
}
__global__ void fill_kernel(const int* __restrict__ edge, int E) {
    GDC_WAIT();
    GDC_TRIGGER();
    int e = blockIdx.x * blockDim.x + threadIdx.x;
    if (e < E) {
        int r = __ldg(edge + e);
        int c = __ldg(edge + E + e);
        int pos = atomicAdd(&g_cursor[c], 1);
        g_src[pos] = r;
    }
}

__device__ __forceinline__ void write_split4(uint32_t* hi, uint32_t* lo, int idx2, float4 v) {
    uint32_t p0 = bf16pair(v.x, v.y);
    uint32_t p1 = bf16pair(v.z, v.w);
    uint32_t q0 = bf16pair(v.x - lo_f(p0), v.y - hi_f(p0));
    uint32_t q1 = bf16pair(v.z - lo_f(p1), v.w - hi_f(p1));
    reinterpret_cast<uint2*>(hi)[idx2] = make_uint2(p0, p1);
    reinterpret_cast<uint2*>(lo)[idx2] = make_uint2(q0, q1);
}

// ---------------- gather: one warp per node; writes bf16 split A rows ----------------
// SRC=0 (layer 0): rows from g_eh (fp16 emb) via x_idx; root row likewise
// SRC=1 (SGConv):  rows from g_zh (fp16 z, dis-prescaled)
template <int SRC>
__global__ void gather_kernel(const int* __restrict__ x_idx, int N) {
    GDC_WAIT();
    GDC_TRIGGER();
    int t = blockIdx.x * blockDim.x + threadIdx.x;
    int n = t >> 5;
    if (n >= N) return;
    int lane = t & 31;
    int s = __ldg(&g_start[n]);
    int e = __ldg(&g_start[n + 1]);
    float4 a0 = make_float4(0.f, 0.f, 0.f, 0.f);
    float4 a1 = make_float4(0.f, 0.f, 0.f, 0.f);
    const uint2* Z = reinterpret_cast<const uint2*>((SRC == 0) ? g_eh : g_zh);
    int i = s;
    for (; i + 2 <= e; i += 2) {
        int r0 = __ldg(&g_src[i]);
        int r1 = __ldg(&g_src[i + 1]);
        if (SRC == 0) {
            r0 = __ldg(x_idx + r0);
            r1 = __ldg(x_idx + r1);
        }
        uint2 u0 = __ldg(Z + (size_t)r0 * 32 + lane);
        uint2 u1 = __ldg(Z + (size_t)r1 * 32 + lane);
        float4 v0 = h2f4(u0);
        float4 v1 = h2f4(u1);
        a0.x += v0.x; a0.y += v0.y; a0.z += v0.z; a0.w += v0.w;
        a1.x += v1.x; a1.y += v1.y; a1.z += v1.z; a1.w += v1.w;
    }
    if (i < e) {
        int r0 = __ldg(&g_src[i]);
        if (SRC == 0) r0 = __ldg(x_idx + r0);
        uint2 u0 = __ldg(Z + (size_t)r0 * 32 + lane);
        float4 v0 = h2f4(u0);
        a0.x += v0.x; a0.y += v0.y; a0.z += v0.z; a0.w += v0.w;
    }
    a0.x += a1.x; a0.y += a1.y; a0.z += a1.z; a0.w += a1.w;

    uint32_t* Ah = g_ahi + (size_t)n * 128;
    uint32_t* Al = g_alo + (size_t)n * 128;

    if (SRC == 0) {
        float sc = g_deg_inv[n];
        write_split4(Ah, Al, lane,
                     make_float4(sc * a0.x, sc * a0.y, sc * a0.z, sc * a0.w));
        int rn = __ldg(x_idx + n);
        uint2 ur = __ldg(Z + (size_t)rn * 32 + lane);
        write_split4(Ah, Al, 32 + lane, h2f4(ur));
    } else {
        float sc = g_dis[n];
        uint2 uz = __ldg(Z + (size_t)n * 32 + lane);
        float4 z = h2f4(uz);
        write_split4(Ah, Al, lane,
                     make_float4(sc * (a0.x + z.x), sc * (a0.y + z.y),
                                 sc * (a0.z + z.z), sc * (a0.w + z.w)));
    }
}

// ---------------- mma.sync GEMM: 128x128 tile per block, bf16 3-term split ----------------
// smem rows padded to 17 x 16B (272B) -> conflict-free ldmatrix
#define SROW 272
#define OFF_AHI 0
#define OFF_ALO 34816
#define OFF_BHI 69632
#define OFF_BLO 104448
#define SMEM_BYTES 139264

template <int KCHUNKS, bool STATS, bool BIAS>
__global__ __launch_bounds__(256, 1)
void mma_kernel(const float* __restrict__ bias, float* __restrict__ H,
                float* __restrict__ stats, int N, int bsel) {
    extern __shared__ __align__(16) char smem[];
    __shared__ float sstats[256];

    GDC_WAIT();
    GDC_TRIGGER();

    const int tid = threadIdx.x;
    const int wid = tid >> 5;
    const int lane = tid & 31;
    const int tile = blockIdx.x;
    const int warpRow = wid & 3;        // 4 row groups of 32
    const int warpCol = wid >> 2;       // 2 col groups of 64

    sstats[tid] = 0.f;

    const uint32_t smemu = smem_u32(smem);

    float acc[2][8][4];
#pragma unroll
    for (int mt = 0; mt < 2; mt++)
#pragma unroll
        for (int nt = 0; nt < 8; nt++)
#pragma unroll
            for (int q = 0; q < 4; q++) acc[mt][nt][q] = 0.f;

    uint32_t aAddr[2][2];   // [mt][hi/lo]
#pragma unroll
    for (int mt = 0; mt < 2; mt++) {
        uint32_t rb = (uint32_t)(warpRow * 32 + mt * 16 + (lane & 15)) * SROW + ((lane >> 4) << 4);
        aAddr[mt][0] = smemu + OFF_AHI + rb;
        aAddr[mt][1] = smemu + OFF_ALO + rb;
    }
    uint32_t bRow = (uint32_t)(warpCol * 64 + (lane & 7)) * SROW + (((lane >> 3) & 1) << 4);
    uint32_t bAddrHi = smemu + OFF_BHI + bRow;
    uint32_t bAddrLo = smemu + OFF_BLO + bRow;

#pragma unroll
    for (int c = 0; c < KCHUNKS; c++) {
        __syncthreads();
        {
            const int4* gAh = (const int4*)(g_ahi + ((size_t)tile * 128) * 128) + c * 16;
            const int4* gAl = (const int4*)(g_alo + ((size_t)tile * 128) * 128) + c * 16;
            const int4* gBh = (const int4*)(g_bhi[bsel + c]);
            const int4* gBl = (const int4*)(g_blo[bsel + c]);
            int4* sAh = (int4*)(smem + OFF_AHI);
            int4* sAl = (int4*)(smem + OFF_ALO);
            int4* sBh = (int4*)(smem + OFF_BHI);
            int4* sBl = (int4*)(smem + OFF_BLO);
#pragma unroll
            for (int it = 0; it < 8; it++) {
                int idx = tid + it * 256;           // 0..2047
                int r = idx >> 4;
                int ch = idx & 15;
                int sIdx = r * 17 + ch;
                sAh[sIdx] = __ldg(gAh + r * 32 + ch);   // A global row stride 512B = 32 int4
                sAl[sIdx] = __ldg(gAl + r * 32 + ch);
                sBh[sIdx] = __ldg(gBh + r * 16 + ch);   // B global row stride 256B = 16 int4
                sBl[sIdx] = __ldg(gBl + r * 16 + ch);
            }
        }
        __syncthreads();

#pragma unroll
        for (int ks = 0; ks < 8; ks++) {
            uint32_t ahi[2][4], alo[2][4];
#pragma unroll
            for (int mt = 0; mt < 2; mt++) {
                ldmx4(ahi[mt], aAddr[mt][0] + ks * 32);
                ldmx4(alo[mt], aAddr[mt][1] + ks * 32);
            }
#pragma unroll
            for (int nt = 0; nt < 8; nt++) {
                uint32_t bhi[2], blo[2];
                ldmx2(bhi, bAddrHi + nt * (8 * SROW) + ks * 32);
                ldmx2(blo, bAddrLo + nt * (8 * SROW) + ks * 32);
#pragma unroll
                for (int mt = 0; mt < 2; mt++) {
                    mma16816(acc[mt][nt], ahi[mt], bhi);
                    mma16816(acc[mt][nt], ahi[mt], blo);
                    mma16816(acc[mt][nt], alo[mt], bhi);
                }
            }
        }
    }

    // ---- epilogue: bias + store + BN stats ----
    const int rowbase = tile * 128 + warpRow * 32;
    const int colbase = warpCol * 64;

    float s[8][2], q[8][2];
#pragma unroll
    for (int nt = 0; nt < 8; nt++) { s[nt][0] = s[nt][1] = 0.f; q[nt][0] = q[nt][1] = 0.f; }

#pragma unroll
    for (int mt = 0; mt < 2; mt++) {
        int r0 = rowbase + mt * 16 + (lane >> 2);
        int r1 = r0 + 8;
#pragma unroll
        for (int nt = 0; nt < 8; nt++) {
            int col = colbase + nt * 8 + ((lane & 3) << 1);
            float b0 = BIAS ? __ldg(bias + col) : 0.f;
            float b1 = BIAS ? __ldg(bias + col + 1) : 0.f;
            float v0 = acc[mt][nt][0] + b0;
            float v1 = acc[mt][nt][1] + b1;
            float v2 = acc[mt][nt][2] + b0;
            float v3 = acc[mt][nt][3] + b1;
            if (r0 < N) {
                *(float2*)(H + (size_t)r0 * DIM + col) = make_float2(v0, v1);
                if (STATS) {
                    s[nt][0] += v0; s[nt][1] += v1;
                    q[nt][0] += v0 * v0; q[nt][1] += v1 * v1;
                }
            }
            if (r1 < N) {
                *(float2*)(H + (size_t)r1 * DIM + col) = make_float2(v2, v3);
                if (STATS) {
                    s[nt][0] += v2; s[nt][1] += v3;
                    q[nt][0] += v2 * v2; q[nt][1] += v3 * v3;
                }
            }
        }
    }

    if (STATS) {
#pragma unroll
        for (int nt = 0; nt < 8; nt++) {
#pragma unroll
            for (int p = 0; p < 2; p++) {
                float vs = s[nt][p], vq = q[nt][p];
#pragma unroll
                for (int sh = 4; sh < 32; sh <<= 1) {
                    vs += __shfl_xor_sync(0xFFFFFFFFu, vs, sh);
                    vq += __shfl_xor_sync(0xFFFFFFFFu, vq, sh);
                }
                if (lane < 4) {
                    int col = colbase + nt * 8 + (lane << 1) + p;
                    atomicAdd(&sstats[col], vs);
                    atomicAdd(&sstats[128 + col], vq);
                }
            }
        }
        __syncthreads();
        atomicAdd(&stats[tid], sstats[tid]);
    }
}

// ---------------- BN apply + ReLU + dis-prescale; z stored as half2 ----------------
__global__ void bn_apply_kernel(const float* __restrict__ gamma, const float* __restrict__ beta,
                                const float* __restrict__ stats, int N) {
    __shared__ float4 ssc[32], ssh[32];
    GDC_WAIT();
    GDC_TRIGGER();
    int tid = threadIdx.x;
    if (tid < 32) {
        float4 s = ((const float4*)stats)[tid];
        float4 sq = ((const float4*)stats)[32 + tid];
        float4 g = __ldg((const float4*)gamma + tid);
        float4 b = __ldg((const float4*)beta + tid);
        float invn = 1.0f / (float)N;
        float4 mu = make_float4(s.x * invn, s.y * invn, s.z * invn, s.w * invn);
        float4 sc, sh;
        sc.x = g.x * rsqrtf(fmaxf(sq.x * invn - mu.x * mu.x, 0.f) + BN_EPS);
        sc.y = g.y * rsqrtf(fmaxf(sq.y * invn - mu.y * mu.y, 0.f) + BN_EPS);
        sc.z = g.z * rsqrtf(fmaxf(sq.z * invn - mu.z * mu.z, 0.f) + BN_EPS);
        sc.w = g.w * rsqrtf(fmaxf(sq.w * invn - mu.w * mu.w, 0.f) + BN_EPS);
        sh.x = b.x - mu.x * sc.x;
        sh.y = b.y - mu.y * sc.y;
        sh.z = b.z - mu.z * sc.z;
        sh.w = b.w - mu.w * sc.w;
        ssc[tid] = sc; ssh[tid] = sh;
    }
    __syncthreads();
    int i = blockIdx.x * blockDim.x + tid;
    int tot = N * (DIM / 4);
    if (i >= tot) return;
    int n = i >> 5;
    int q = i & 31;
    float4 h = reinterpret_cast<const float4*>(g_h)[i];
    float4 sc = ssc[q];
    float4 sh = ssh[q];
    float d = g_dis[n];
    float4 z;
    z.x = d * fmaxf(fmaf(h.x, sc.x, sh.x), 0.f);
    z.y = d * fmaxf(fmaf(h.y, sc.y, sh.y), 0.f);
    z.z = d * fmaxf(fmaf(h.z, sc.z, sh.z), 0.f);
    z.w = d * fmaxf(fmaf(h.w, sc.w, sh.w), 0.f);
    reinterpret_cast<uint2*>(g_zh)[i] = f4h2(z);
}

// ---------------- PDL launch helpers ----------------
static inline void launch_pdl(void* func, dim3 grid, dim3 block, size_t smem,
                              void** args) {
    cudaLaunchConfig_t cfg = {};
    cfg.gridDim = grid;
    cfg.blockDim = block;
    cfg.dynamicSmemBytes = smem;
    cudaLaunchAttribute attr[1];
    attr[0].id = cudaLaunchAttributeProgrammaticStreamSerialization;
    attr[0].val.programmaticStreamSerializationAllowed = 1;
    cfg.attrs = attr;
    cfg.numAttrs = 1;
    cudaLaunchKernelExC(&cfg, func, args);
}

// ---------------- launch ----------------
extern "C" void kernel_launch(void* const* d_in, const int* in_sizes, int n_in,
                              void* d_out, int out_size) {
    const int*   x_idx  = (const int*)d_in[0];
    const int*   edge   = (const int*)d_in[1];
    const float* emb    = (const float*)d_in[2];
    const float* W_out  = (const float*)d_in[3];
    const float* W_root = (const float*)d_in[4];
    const float* bn0_g  = (const float*)d_in[5];
    const float* bn0_b  = (const float*)d_in[6];
    const float* W_sg1  = (const float*)d_in[7];
    const float* b_sg1  = (const float*)d_in[8];
    const float* bn1_g  = (const float*)d_in[9];
    const float* bn1_b  = (const float*)d_in[10];
    const float* W_sg2  = (const float*)d_in[11];
    const float* b_sg2  = (const float*)d_in[12];
    float* out = (float*)d_out;

    int N = in_sizes[0];
    int E = in_sizes[1] / 2;

    void* hp = nullptr;   cudaGetSymbolAddress(&hp, g_h);
    void* sp = nullptr;   cudaGetSymbolAddress(&sp, g_stats);
    float* Hbuf = (float*)hp;
    float* stats0 = (float*)sp;
    float* stats1 = stats0 + 256;

    cudaFuncSetAttribute(mma_kernel<2, true, false>, cudaFuncAttributeMaxDynamicSharedMemorySize, SMEM_BYTES);
    cudaFuncSetAttribute(mma_kernel<1, true, true>,  cudaFuncAttributeMaxDynamicSharedMemorySize, SMEM_BYTES);
    cudaFuncSetAttribute(mma_kernel<1, false, true>, cudaFuncAttributeMaxDynamicSharedMemorySize, SMEM_BYTES);

    const int nbElem = (N * (DIM / 4) + 255) / 256;
    const int nbNode = (N + 255) / 256;
    const int nbEdgeT = (E + 255) / 256;
    const int nbGath = (N * 32 + 255) / 256;
    const int nbScan = (N + 1023) / 1024;
    const int nbConv = (N * 32 + 255) / 256;
    const int NT = (N + 127) / 128;
    const dim3 blk(256);

    // CSR build + norms + weight images + emb fp16 table
    {
        void* a[] = { (void*)&N };
        launch_pdl((void*)init_zero_kernel, dim3(nbNode), blk, 0, a);
    }
    {
        const int* colp = edge + E;
        void* a[] = { (void*)&colp, (void*)&E, (void*)&nbEdgeT, (void*)&N, (void*)&emb,
                      (void*)&W_out, (void*)&W_root, (void*)&W_sg1, (void*)&W_sg2 };
        launch_pdl((void*)deg_bprep_kernel, dim3(nbEdgeT + 128 + nbConv), blk, 0, a);
    }
    {
        void* a[] = { (void*)&N };
        launch_pdl((void*)scan1_kernel, dim3(nbScan), blk, 0, a);
    }
    {
        void* a[] = { (void*)&N, (void*)&E };
        launch_pdl((void*)scan3_kernel, dim3(nbScan), blk, 0, a);
    }
    {
        void* a[] = { (void*)&edge, (void*)&E };
        launch_pdl((void*)fill_kernel, dim3(nbEdgeT), blk, 0, a);
    }

    // layer 0: ClusterGCN -> BN -> ReLU
    {
        void* a[] = { (void*)&x_idx, (void*)&N };
        launch_pdl((void*)gather_kernel<0>, dim3(nbGath), blk, 0, a);
    }
    {
        const float* bias = nullptr; int bsel = 0;
        void* a[] = { (void*)&bias, (void*)&Hbuf, (void*)&stats0, (void*)&N, (void*)&bsel };
        launch_pdl((void*)mma_kernel<2, true, false>, dim3(NT), blk, SMEM_BYTES, a);
    }
    {
        void* a[] = { (void*)&bn0_g, (void*)&bn0_b, (void*)&stats0, (void*)&N };
        launch_pdl((void*)bn_apply_kernel, dim3(nbElem), blk, 0, a);
    }

    // layer 1: SGConv -> BN -> ReLU
    {
        void* a[] = { (void*)&x_idx, (void*)&N };
        launch_pdl((void*)gather_kernel<1>, dim3(nbGath), blk, 0, a);
    }
    {
        int bsel = 2;
        void* a[] = { (void*)&b_sg1, (void*)&Hbuf, (void*)&stats1, (void*)&N, (void*)&bsel };
        launch_pdl((void*)mma_kernel<1, true, true>, dim3(NT), blk, SMEM_BYTES, a);
    }
    {
        void* a[] = { (void*)&bn1_g, (void*)&bn1_b, (void*)&stats1, (void*)&N };
        launch_pdl((void*)bn_apply_kernel, dim3(nbElem), blk, 0, a);
    }

    // layer 2: final SGConv -> d_out
    {
        void* a[] = { (void*)&x_idx, (void*)&N };
        launch_pdl((void*)gather_kernel<1>, dim3(nbGath), blk, 0, a);
    }
    {
        float* snull = nullptr; int bsel = 3;
        void* a[] = { (void*)&b_sg2, (void*)&out, (void*)&snull, (void*)&N, (void*)&bsel };
        launch_pdl((void*)mma_kernel<1, false, true>, dim3(NT), blk, SMEM_BYTES, a);
    }
}